// round 7
// baseline (speedup 1.0000x reference)
#include <cuda_runtime.h>
#include <cuda_bf16.h>
#include <math.h>
#include <stdint.h>

// ---------------------------------------------------------------------------
// TransformerXL RPE via bf16x3 (emulated fp32) mma.sync GEMMs.
// out[b,i,j] = ( (Q+u)[b,i,:]·K[b,j,:] + A[b,i, clip(i-j)+M] ) / sqrt(D)
// Q = x@Wq^T, K = x@Wk^T, R = table@Wr^T, A = (Q+v)@R^T.
// Split a = hi + lo (bf16); a*b ~= ah*bh + ah*bl + al*bh, fp32 accumulate.
// CTA 128x128, 512 threads (4x4 warps of 32x32), BK=64, 3-stage cp.async.
// ---------------------------------------------------------------------------

#define SDIV(a,b) (((a)+(b)-1)/(b))

static constexpr int STG      = 3;
static constexpr int TILE_B   = 128 * 128;        // 128 rows x 64 bf16 = 16 KB
static constexpr int STAGE_B  = 4 * TILE_B;       // Ah, Al, Bh, Bl
static constexpr int SMEM_REQ = STG * STAGE_B;    // 192 KB
static constexpr int LDP      = 1028;             // padded ld for A (pos) matrix
static constexpr int NT       = 512;              // threads per CTA

// ---------------- scratch (B=4, L=2048, D=1024, 2M+1=1025) -----------------
__device__ __align__(1024) __nv_bfloat16 g_xh [8192u*1024u];
__device__ __align__(1024) __nv_bfloat16 g_xl [8192u*1024u];
__device__ __align__(1024) __nv_bfloat16 g_wqh[1024u*1024u];
__device__ __align__(1024) __nv_bfloat16 g_wql[1024u*1024u];
__device__ __align__(1024) __nv_bfloat16 g_wkh[1024u*1024u];
__device__ __align__(1024) __nv_bfloat16 g_wkl[1024u*1024u];
__device__ __align__(1024) __nv_bfloat16 g_wrh[1024u*1024u];
__device__ __align__(1024) __nv_bfloat16 g_wrl[1024u*1024u];
__device__ __align__(1024) __nv_bfloat16 g_tbh[1025u*1024u];
__device__ __align__(1024) __nv_bfloat16 g_tbl[1025u*1024u];
__device__ __align__(1024) __nv_bfloat16 g_quh[8192u*1024u];
__device__ __align__(1024) __nv_bfloat16 g_qul[8192u*1024u];
__device__ __align__(1024) __nv_bfloat16 g_qvh[8192u*1024u];
__device__ __align__(1024) __nv_bfloat16 g_qvl[8192u*1024u];
__device__ __align__(1024) __nv_bfloat16 g_kh [8192u*1024u];
__device__ __align__(1024) __nv_bfloat16 g_kl [8192u*1024u];
__device__ __align__(1024) __nv_bfloat16 g_rh [1025u*1024u];
__device__ __align__(1024) __nv_bfloat16 g_rl [1025u*1024u];
__device__ __align__(1024) float         g_A  [8192u*(unsigned)LDP];

// ---------------------------- PTX helpers ----------------------------------
__device__ __forceinline__ uint32_t smem_u32(const void* p) {
    uint32_t a;
    asm("{ .reg .u64 t; cvta.to.shared.u64 t, %1; cvt.u32.u64 %0, t; }" : "=r"(a) : "l"(p));
    return a;
}
#define CP_ASYNC16(dst, src, pbytes) \
    asm volatile("cp.async.cg.shared.global [%0], [%1], 16, %2;" \
                 :: "r"(dst), "l"(src), "r"(pbytes))
#define CP_COMMIT() asm volatile("cp.async.commit_group;" ::: "memory")
#define CP_WAIT1()  asm volatile("cp.async.wait_group 1;"  ::: "memory")

#define LDSM_X4(r0,r1,r2,r3,a) \
    asm volatile("ldmatrix.sync.aligned.m8n8.x4.shared.b16 {%0,%1,%2,%3}, [%4];" \
                 : "=r"(r0), "=r"(r1), "=r"(r2), "=r"(r3) : "r"(a))
#define LDSM_X2(r0,r1,a) \
    asm volatile("ldmatrix.sync.aligned.m8n8.x2.shared.b16 {%0,%1}, [%2];" \
                 : "=r"(r0), "=r"(r1) : "r"(a))
#define MMA16816(c, a, b) \
    asm volatile("mma.sync.aligned.m16n8k16.row.col.f32.bf16.bf16.f32 " \
                 "{%0,%1,%2,%3}, {%4,%5,%6,%7}, {%8,%9}, {%0,%1,%2,%3};" \
                 : "+f"((c)[0]), "+f"((c)[1]), "+f"((c)[2]), "+f"((c)[3]) \
                 : "r"((a)[0]), "r"((a)[1]), "r"((a)[2]), "r"((a)[3]), \
                   "r"((b)[0]), "r"((b)[1]))

__device__ __forceinline__ void split2(float a, __nv_bfloat16& h, __nv_bfloat16& l) {
    h = __float2bfloat16(a);
    l = __float2bfloat16(a - __bfloat162float(h));
}

// ------------------- fused split kernel (one launch, 5 segments) ------------
__global__ void split5(const float* __restrict__ i0, const float* __restrict__ i1,
                       const float* __restrict__ i2, const float* __restrict__ i3,
                       const float* __restrict__ i4,
                       __nv_bfloat16* __restrict__ h0, __nv_bfloat16* __restrict__ l0,
                       __nv_bfloat16* __restrict__ h1, __nv_bfloat16* __restrict__ l1,
                       __nv_bfloat16* __restrict__ h2, __nv_bfloat16* __restrict__ l2,
                       __nv_bfloat16* __restrict__ h3, __nv_bfloat16* __restrict__ l3,
                       __nv_bfloat16* __restrict__ h4, __nv_bfloat16* __restrict__ l4,
                       int p0, int p1, int p2, int p3)
{
    int b = blockIdx.x;
    const float* in; __nv_bfloat16 *hi, *lo;
    if      (b < p0) { in = i0; hi = h0; lo = l0; }
    else if (b < p1) { in = i1; hi = h1; lo = l1; b -= p0; }
    else if (b < p2) { in = i2; hi = h2; lo = l2; b -= p1; }
    else if (b < p3) { in = i3; hi = h3; lo = l3; b -= p2; }
    else             { in = i4; hi = h4; lo = l4; b -= p3; }

    const int i = b * blockDim.x + threadIdx.x;
    float4 v = reinterpret_cast<const float4*>(in)[i];
    __nv_bfloat16 a0,b0,a1,b1,a2,b2,a3,b3;
    split2(v.x,a0,b0); split2(v.y,a1,b1); split2(v.z,a2,b2); split2(v.w,a3,b3);
    reinterpret_cast<__nv_bfloat162*>(hi)[i*2+0] = __halves2bfloat162(a0,a1);
    reinterpret_cast<__nv_bfloat162*>(hi)[i*2+1] = __halves2bfloat162(a2,a3);
    reinterpret_cast<__nv_bfloat162*>(lo)[i*2+0] = __halves2bfloat162(b0,b1);
    reinterpret_cast<__nv_bfloat162*>(lo)[i*2+1] = __halves2bfloat162(b2,b3);
}

// ---------------------- tile loader (cp.async, swizzled) --------------------
// Tile: 128 rows x 64 bf16 (128 B rows). Chunk c (16 B) of row r stored at
// r*128 + ((c ^ (r&7))*16)  -> conflict-free for both cp.async and ldmatrix.
__device__ __forceinline__ void load_tile(uint32_t dst, const __nv_bfloat16* g,
                                          int row0, int rows_max, int k0, int ld,
                                          int tid, bool bchk) {
#pragma unroll
    for (int i = 0; i < 2; i++) {
        const int idx = tid + i * NT;
        const int r = idx >> 3, c = idx & 7;
        int row = row0 + r;
        unsigned p = 16;
        if (bchk && row >= rows_max) { p = 0; row = 0; }
        const __nv_bfloat16* src = g + (size_t)row * ld + k0 + c * 8;
        const uint32_t d = dst + r * 128 + (((c ^ (r & 7))) << 4);
        CP_ASYNC16(d, src, p);
    }
}

// ------------------------------ GEMM kernel ---------------------------------
// MODE 0: fp32 store (ldc)                                   [GEMM4 -> A]
// MODE 1: (acc+bias1)->C0/C1 hi/lo, (acc+bias2)->C2/C3 hi/lo [GEMM1]
// MODE 3: acc -> C0/C1 hi/lo                                 [GEMM2, GEMM3]
// MODE 2: (acc + Apos[m, clip(m-n)+mr]) * scale -> C0        [GEMM5, batched]
template <int MODE, bool BCHK>
__global__ __launch_bounds__(NT, 1)
void tc_gemm(const __nv_bfloat16* __restrict__ gAh, const __nv_bfloat16* __restrict__ gAl,
             const __nv_bfloat16* __restrict__ gBh, const __nv_bfloat16* __restrict__ gBl,
             void* C0, void* C1, void* C2, void* C3,
             const float* __restrict__ bias1, const float* __restrict__ bias2,
             const float* __restrict__ Apos,
             int M, int N, int ld, int ldc, int rowOffA, int rowOffB,
             long long sC, long long sP, int maxrel, int ldp, float scale, int nk)
{
    extern __shared__ __align__(128) char smem_raw[];
    const uint32_t sb = smem_u32(smem_raw);
    const int tid = threadIdx.x, lane = tid & 31, wid = tid >> 5;
    const int bm = blockIdx.y * 128, bn = blockIdx.x * 128, bz = blockIdx.z;
    const int wm = wid >> 2, wn = wid & 3;            // warp grid 4 x 4
    const int rA = bz * rowOffA + bm;
    const int rB = bz * rowOffB + bn;

    float acc[2][4][4];
#pragma unroll
    for (int mi = 0; mi < 2; mi++)
#pragma unroll
        for (int ni = 0; ni < 4; ni++)
#pragma unroll
            for (int q = 0; q < 4; q++) acc[mi][ni][q] = 0.f;

    auto load_stage = [&](int s, int t) {
        const uint32_t base = sb + s * STAGE_B;
        const int k0 = t * 64;
        load_tile(base + 0 * TILE_B, gAh, rA, M, k0, ld, tid, BCHK);
        load_tile(base + 1 * TILE_B, gAl, rA, M, k0, ld, tid, BCHK);
        load_tile(base + 2 * TILE_B, gBh, rB, N, k0, ld, tid, BCHK);
        load_tile(base + 3 * TILE_B, gBl, rB, N, k0, ld, tid, BCHK);
    };

    load_stage(0, 0); CP_COMMIT();
    load_stage(1, 1); CP_COMMIT();

    // ldmatrix source addresses (lane-invariant parts)
    const int a_row = wm * 32 + (lane & 15);          // + mi*16
    const int a_cc  = lane >> 4;                      // + ks*2
    const int b_row = wn * 32 + (lane & 7);           // + ni*8
    const int b_cc  = (lane >> 3) & 1;                // + ks*2

    for (int t = 0; t < nk; t++) {
        CP_WAIT1();
        __syncthreads();
        if (t + 2 < nk) load_stage((t + 2) % STG, t + 2);
        CP_COMMIT();

        const uint32_t base = sb + (t % STG) * STAGE_B;
        const uint32_t sAh = base, sAl = base + TILE_B;
        const uint32_t sBh = base + 2 * TILE_B, sBl = base + 3 * TILE_B;

#pragma unroll
        for (int ks = 0; ks < 4; ks++) {
            uint32_t fAh[2][4], fAl[2][4], fBh[4][2], fBl[4][2];
#pragma unroll
            for (int mi = 0; mi < 2; mi++) {
                const int row = a_row + mi * 16;
                const int cc = ks * 2 + a_cc;
                const uint32_t off = row * 128 + (((cc ^ (row & 7))) << 4);
                LDSM_X4(fAh[mi][0], fAh[mi][1], fAh[mi][2], fAh[mi][3], sAh + off);
                LDSM_X4(fAl[mi][0], fAl[mi][1], fAl[mi][2], fAl[mi][3], sAl + off);
            }
#pragma unroll
            for (int ni = 0; ni < 4; ni++) {
                const int row = b_row + ni * 8;
                const int cc = ks * 2 + b_cc;
                const uint32_t off = row * 128 + (((cc ^ (row & 7))) << 4);
                LDSM_X2(fBh[ni][0], fBh[ni][1], sBh + off);
                LDSM_X2(fBl[ni][0], fBl[ni][1], sBl + off);
            }
#pragma unroll
            for (int mi = 0; mi < 2; mi++)
#pragma unroll
                for (int ni = 0; ni < 4; ni++) MMA16816(acc[mi][ni], fAh[mi], fBh[ni]);
#pragma unroll
            for (int mi = 0; mi < 2; mi++)
#pragma unroll
                for (int ni = 0; ni < 4; ni++) MMA16816(acc[mi][ni], fAh[mi], fBl[ni]);
#pragma unroll
            for (int mi = 0; mi < 2; mi++)
#pragma unroll
                for (int ni = 0; ni < 4; ni++) MMA16816(acc[mi][ni], fAl[mi], fBh[ni]);
        }
    }

    // ------------------------------ epilogue --------------------------------
    const int lr = lane >> 2, lc = (lane & 3) * 2;

#pragma unroll
    for (int mi = 0; mi < 2; mi++) {
#pragma unroll
        for (int ni = 0; ni < 4; ni++) {
            const float* cc = acc[mi][ni];
            const int n = bn + wn * 32 + ni * 8 + lc;
#pragma unroll
            for (int h = 0; h < 2; h++) {
                const int m = bm + wm * 32 + mi * 16 + lr + h * 8;
                const float v0 = cc[h * 2 + 0], v1 = cc[h * 2 + 1];
                if (MODE == 0) {
                    if (BCHK && m >= M) continue;
                    float* Cf = (float*)C0;
                    if (!BCHK || n + 1 < N) {
                        *reinterpret_cast<float2*>(Cf + (size_t)m * ldc + n) = make_float2(v0, v1);
                    } else if (n < N) {
                        Cf[(size_t)m * ldc + n] = v0;
                    }
                } else if (MODE == 3) {
                    if (BCHK && m >= M) continue;
                    __nv_bfloat16* Ch = (__nv_bfloat16*)C0;
                    __nv_bfloat16* Cl = (__nv_bfloat16*)C1;
                    __nv_bfloat16 h0, l0, h1, l1;
                    split2(v0, h0, l0); split2(v1, h1, l1);
                    const size_t o = (size_t)m * ldc + n;
                    *reinterpret_cast<__nv_bfloat162*>(Ch + o) = __halves2bfloat162(h0, h1);
                    *reinterpret_cast<__nv_bfloat162*>(Cl + o) = __halves2bfloat162(l0, l1);
                } else if (MODE == 1) {
                    __nv_bfloat16* Uh = (__nv_bfloat16*)C0;
                    __nv_bfloat16* Ul = (__nv_bfloat16*)C1;
                    __nv_bfloat16* Vh = (__nv_bfloat16*)C2;
                    __nv_bfloat16* Vl = (__nv_bfloat16*)C3;
                    const size_t o = (size_t)m * ldc + n;
                    __nv_bfloat16 h0, l0, h1, l1;
                    split2(v0 + bias1[n], h0, l0); split2(v1 + bias1[n + 1], h1, l1);
                    *reinterpret_cast<__nv_bfloat162*>(Uh + o) = __halves2bfloat162(h0, h1);
                    *reinterpret_cast<__nv_bfloat162*>(Ul + o) = __halves2bfloat162(l0, l1);
                    split2(v0 + bias2[n], h0, l0); split2(v1 + bias2[n + 1], h1, l1);
                    *reinterpret_cast<__nv_bfloat162*>(Vh + o) = __halves2bfloat162(h0, h1);
                    *reinterpret_cast<__nv_bfloat162*>(Vl + o) = __halves2bfloat162(l0, l1);
                } else { // MODE 2
                    const float* Ap = Apos + (size_t)bz * sP + (size_t)m * ldp + maxrel;
                    float* Ob = (float*)C0 + (size_t)bz * sC + (size_t)m * ldc;
                    int r0 = m - n;
                    r0 = r0 > maxrel ? maxrel : (r0 < -maxrel ? -maxrel : r0);
                    int r1 = m - (n + 1);
                    r1 = r1 > maxrel ? maxrel : (r1 < -maxrel ? -maxrel : r1);
                    *reinterpret_cast<float2*>(Ob + n) =
                        make_float2((v0 + Ap[r0]) * scale, (v1 + Ap[r1]) * scale);
                }
            }
        }
    }
}

// ------------------------------- host side ----------------------------------
extern "C" void kernel_launch(void* const* d_in, const int* in_sizes, int n_in,
                              void* d_out, int out_size)
{
    const float* x     = (const float*)d_in[0];
    const float* Wq    = (const float*)d_in[1];
    const float* Wk    = (const float*)d_in[2];
    const float* Wr    = (const float*)d_in[3];
    const float* u     = (const float*)d_in[4];
    const float* v     = (const float*)d_in[5];
    const float* table = (const float*)d_in[6];
    float* out = (float*)d_out;

    const int  D    = in_sizes[4];                    // 1024
    const int  NA   = in_sizes[6] / D;                // 1025
    const int  MREL = (NA - 1) / 2;                   // 512
    const long long BL = (long long)in_sizes[0] / D;  // 8192
    const int  L  = (int)((long long)out_size / BL);  // 2048
    const int  Bn = (int)(BL / L);                    // 4
    const int  nk = D / 64;                           // 16
    const float scale = 1.f / sqrtf((float)D);

    void *xh,*xl,*wqh,*wql,*wkh,*wkl,*wrh,*wrl,*tbh,*tbl;
    void *quh,*qul,*qvh,*qvl,*kh,*kl,*rh,*rl,*Aa;
    cudaGetSymbolAddress(&xh,  g_xh);  cudaGetSymbolAddress(&xl,  g_xl);
    cudaGetSymbolAddress(&wqh, g_wqh); cudaGetSymbolAddress(&wql, g_wql);
    cudaGetSymbolAddress(&wkh, g_wkh); cudaGetSymbolAddress(&wkl, g_wkl);
    cudaGetSymbolAddress(&wrh, g_wrh); cudaGetSymbolAddress(&wrl, g_wrl);
    cudaGetSymbolAddress(&tbh, g_tbh); cudaGetSymbolAddress(&tbl, g_tbl);
    cudaGetSymbolAddress(&quh, g_quh); cudaGetSymbolAddress(&qul, g_qul);
    cudaGetSymbolAddress(&qvh, g_qvh); cudaGetSymbolAddress(&qvl, g_qvl);
    cudaGetSymbolAddress(&kh,  g_kh);  cudaGetSymbolAddress(&kl,  g_kl);
    cudaGetSymbolAddress(&rh,  g_rh);  cudaGetSymbolAddress(&rl,  g_rl);
    cudaGetSymbolAddress(&Aa,  g_A);

    static bool attr_done = false;
    if (!attr_done) {
        cudaFuncSetAttribute(tc_gemm<1,false>, cudaFuncAttributeMaxDynamicSharedMemorySize, SMEM_REQ);
        cudaFuncSetAttribute(tc_gemm<3,false>, cudaFuncAttributeMaxDynamicSharedMemorySize, SMEM_REQ);
        cudaFuncSetAttribute(tc_gemm<3,true >, cudaFuncAttributeMaxDynamicSharedMemorySize, SMEM_REQ);
        cudaFuncSetAttribute(tc_gemm<0,true >, cudaFuncAttributeMaxDynamicSharedMemorySize, SMEM_REQ);
        cudaFuncSetAttribute(tc_gemm<2,false>, cudaFuncAttributeMaxDynamicSharedMemorySize, SMEM_REQ);
        attr_done = true;
    }

    // ---- fused split: one launch for x, Wq, Wk, Wr, table ----
    {
        const int T = 256;
        const int bx = (int)(BL * D / 4) / T;   // 8192
        const int bw = (D * D / 4) / T;         // 1024
        const int bt = (NA * D / 4) / T;        // 1025
        const int p0 = bx, p1 = p0 + bw, p2 = p1 + bw, p3 = p2 + bw;
        split5<<<p3 + bt, T>>>(x, Wq, Wk, Wr, table,
            (__nv_bfloat16*)xh,  (__nv_bfloat16*)xl,
            (__nv_bfloat16*)wqh, (__nv_bfloat16*)wql,
            (__nv_bfloat16*)wkh, (__nv_bfloat16*)wkl,
            (__nv_bfloat16*)wrh, (__nv_bfloat16*)wrl,
            (__nv_bfloat16*)tbh, (__nv_bfloat16*)tbl,
            p0, p1, p2, p3);
    }

    const dim3 blk(NT);

    // 1) Qu/Qv = x@Wq^T + u/v  -> bf16 hi/lo (MODE 1)
    tc_gemm<1,false><<<dim3(D/128, (int)(BL/128), 1), blk, SMEM_REQ>>>(
        (const __nv_bfloat16*)xh, (const __nv_bfloat16*)xl,
        (const __nv_bfloat16*)wqh, (const __nv_bfloat16*)wql,
        quh, qul, qvh, qvl, u, v, nullptr,
        (int)BL, D, D, D, 0, 0, 0, 0, 0, 0, 0.f, nk);

    // 2) K = x@Wk^T -> bf16 hi/lo (MODE 3)
    tc_gemm<3,false><<<dim3(D/128, (int)(BL/128), 1), blk, SMEM_REQ>>>(
        (const __nv_bfloat16*)xh, (const __nv_bfloat16*)xl,
        (const __nv_bfloat16*)wkh, (const __nv_bfloat16*)wkl,
        kh, kl, nullptr, nullptr, nullptr, nullptr, nullptr,
        (int)BL, D, D, D, 0, 0, 0, 0, 0, 0, 0.f, nk);

    // 3) R = table@Wr^T -> bf16 hi/lo (MODE 3, M bounds 1025)
    tc_gemm<3,true><<<dim3(D/128, SDIV(NA,128), 1), blk, SMEM_REQ>>>(
        (const __nv_bfloat16*)tbh, (const __nv_bfloat16*)tbl,
        (const __nv_bfloat16*)wrh, (const __nv_bfloat16*)wrl,
        rh, rl, nullptr, nullptr, nullptr, nullptr, nullptr,
        NA, D, D, D, 0, 0, 0, 0, 0, 0, 0.f, nk);

    // 4) A = Qv@R^T -> fp32, ldc=LDP (MODE 0, N bounds 1025)
    tc_gemm<0,true><<<dim3(SDIV(NA,128), (int)(BL/128), 1), blk, SMEM_REQ>>>(
        (const __nv_bfloat16*)qvh, (const __nv_bfloat16*)qvl,
        (const __nv_bfloat16*)rh, (const __nv_bfloat16*)rl,
        Aa, nullptr, nullptr, nullptr, nullptr, nullptr, nullptr,
        (int)BL, NA, D, LDP, 0, 0, 0, 0, 0, 0, 0.f, nk);

    // 5) out = (Qu@K^T + gather(A)) * scale, batched over B (MODE 2)
    tc_gemm<2,false><<<dim3(L/128, L/128, Bn), blk, SMEM_REQ>>>(
        (const __nv_bfloat16*)quh, (const __nv_bfloat16*)qul,
        (const __nv_bfloat16*)kh, (const __nv_bfloat16*)kl,
        out, nullptr, nullptr, nullptr, nullptr, nullptr, (const float*)Aa,
        L, L, D, L, L, L,
        (long long)L * L, (long long)L * LDP, MREL, LDP, scale, nk);
}

// round 8
// speedup vs baseline: 1.2823x; 1.2823x over previous
#include <cuda_runtime.h>
#include <cuda_fp16.h>
#include <math.h>
#include <stdint.h>

// ---------------------------------------------------------------------------
// TransformerXL RPE via fp16 split-precision mma.sync GEMMs.
// out[b,i,j] = ( (Q+u)[b,i,:]·K[b,j,:] + A[b,i, clip(i-j)+M] ) / sqrt(D)
// Q = x@Wq^T, K = x@Wk^T, R = table@Wr^T, A = (Q+v)@R^T.
// Split a = hi + lo (fp16, 11-bit mantissa each -> ~22-bit combined).
// 3-term GEMMs (chain-critical):   a*b ~= ah*bh + ah*bl + al*bh  (err ~1e-6)
// 2-term GEMMs (G2/G4/G5):         a*b ~= ah*bh + al*bh = a*bh   (err ~2e-4)
// Proven R6 loop: CTA 128x128, warp 64x32, BK=64, 3-stage cp.async, 256 thr.
// ---------------------------------------------------------------------------

#define SDIV(a,b) (((a)+(b)-1)/(b))

static constexpr int STG      = 3;
static constexpr int TILE_B   = 128 * 128;        // 128 rows x 64 fp16 = 16 KB
static constexpr int STAGE_B  = 4 * TILE_B;       // Ah, Al, Bh, Bl slots
static constexpr int SMEM_REQ = STG * STAGE_B;    // 192 KB
static constexpr int LDP      = 1028;             // padded ld for A (pos) matrix

// ---------------- scratch (B=4, L=2048, D=1024, 2M+1=1025) -----------------
__device__ __align__(1024) __half g_xh [8192u*1024u];
__device__ __align__(1024) __half g_xl [8192u*1024u];
__device__ __align__(1024) __half g_wqh[1024u*1024u];
__device__ __align__(1024) __half g_wql[1024u*1024u];
__device__ __align__(1024) __half g_wkh[1024u*1024u];
__device__ __align__(1024) __half g_wkl[1024u*1024u];
__device__ __align__(1024) __half g_wrh[1024u*1024u];
__device__ __align__(1024) __half g_wrl[1024u*1024u];
__device__ __align__(1024) __half g_tbh[1025u*1024u];
__device__ __align__(1024) __half g_tbl[1025u*1024u];
__device__ __align__(1024) __half g_quh[8192u*1024u];
__device__ __align__(1024) __half g_qul[8192u*1024u];
__device__ __align__(1024) __half g_qvh[8192u*1024u];
__device__ __align__(1024) __half g_qvl[8192u*1024u];
__device__ __align__(1024) __half g_kh [8192u*1024u];
__device__ __align__(1024) __half g_kl [8192u*1024u];
__device__ __align__(1024) __half g_rh [1025u*1024u];
__device__ __align__(1024) __half g_rl [1025u*1024u];
__device__ __align__(1024) float  g_A  [8192u*(unsigned)LDP];

// ---------------------------- PTX helpers ----------------------------------
__device__ __forceinline__ uint32_t smem_u32(const void* p) {
    uint32_t a;
    asm("{ .reg .u64 t; cvta.to.shared.u64 t, %1; cvt.u32.u64 %0, t; }" : "=r"(a) : "l"(p));
    return a;
}
#define CP_ASYNC16(dst, src, pbytes) \
    asm volatile("cp.async.cg.shared.global [%0], [%1], 16, %2;" \
                 :: "r"(dst), "l"(src), "r"(pbytes))
#define CP_COMMIT() asm volatile("cp.async.commit_group;" ::: "memory")
#define CP_WAIT1()  asm volatile("cp.async.wait_group 1;"  ::: "memory")

#define LDSM_X4(r0,r1,r2,r3,a) \
    asm volatile("ldmatrix.sync.aligned.m8n8.x4.shared.b16 {%0,%1,%2,%3}, [%4];" \
                 : "=r"(r0), "=r"(r1), "=r"(r2), "=r"(r3) : "r"(a))
#define LDSM_X2(r0,r1,a) \
    asm volatile("ldmatrix.sync.aligned.m8n8.x2.shared.b16 {%0,%1}, [%2];" \
                 : "=r"(r0), "=r"(r1) : "r"(a))
#define MMA16816(c, a, b) \
    asm volatile("mma.sync.aligned.m16n8k16.row.col.f32.f16.f16.f32 " \
                 "{%0,%1,%2,%3}, {%4,%5,%6,%7}, {%8,%9}, {%0,%1,%2,%3};" \
                 : "+f"((c)[0]), "+f"((c)[1]), "+f"((c)[2]), "+f"((c)[3]) \
                 : "r"((a)[0]), "r"((a)[1]), "r"((a)[2]), "r"((a)[3]), \
                   "r"((b)[0]), "r"((b)[1]))

__device__ __forceinline__ void split2h(float a, __half& h, __half& l) {
    h = __float2half_rn(a);
    l = __float2half_rn(a - __half2float(h));
}

// ------------------- fused split kernel (one launch, 5 segments) ------------
__global__ void split5(const float* __restrict__ i0, const float* __restrict__ i1,
                       const float* __restrict__ i2, const float* __restrict__ i3,
                       const float* __restrict__ i4,
                       __half* __restrict__ h0, __half* __restrict__ l0,
                       __half* __restrict__ h1, __half* __restrict__ l1,
                       __half* __restrict__ h2, __half* __restrict__ l2,
                       __half* __restrict__ h3, __half* __restrict__ l3,
                       __half* __restrict__ h4, __half* __restrict__ l4,
                       int p0, int p1, int p2, int p3)
{
    int b = blockIdx.x;
    const float* in; __half *hi, *lo;
    if      (b < p0) { in = i0; hi = h0; lo = l0; }
    else if (b < p1) { in = i1; hi = h1; lo = l1; b -= p0; }
    else if (b < p2) { in = i2; hi = h2; lo = l2; b -= p1; }
    else if (b < p3) { in = i3; hi = h3; lo = l3; b -= p2; }
    else             { in = i4; hi = h4; lo = l4; b -= p3; }

    const int i = b * blockDim.x + threadIdx.x;
    float4 v = reinterpret_cast<const float4*>(in)[i];
    __half a0,b0,a1,b1,a2,b2,a3,b3;
    split2h(v.x,a0,b0); split2h(v.y,a1,b1); split2h(v.z,a2,b2); split2h(v.w,a3,b3);
    reinterpret_cast<__half2*>(hi)[i*2+0] = __halves2half2(a0,a1);
    reinterpret_cast<__half2*>(hi)[i*2+1] = __halves2half2(a2,a3);
    reinterpret_cast<__half2*>(lo)[i*2+0] = __halves2half2(b0,b1);
    reinterpret_cast<__half2*>(lo)[i*2+1] = __halves2half2(b2,b3);
}

// ---------------------- tile loader (cp.async, swizzled) --------------------
// Tile: 128 rows x 64 fp16 (128 B rows). Chunk c (16 B) of row r stored at
// r*128 + ((c ^ (r&7))*16)  -> conflict-free for both cp.async and ldmatrix.
__device__ __forceinline__ void load_tile(uint32_t dst, const __half* g,
                                          int row0, int rows_max, int k0, int ld,
                                          int tid, bool bchk) {
#pragma unroll
    for (int i = 0; i < 4; i++) {
        const int idx = tid + i * 256;
        const int r = idx >> 3, c = idx & 7;
        int row = row0 + r;
        unsigned p = 16;
        if (bchk && row >= rows_max) { p = 0; row = 0; }
        const __half* src = g + (size_t)row * ld + k0 + c * 8;
        const uint32_t d = dst + r * 128 + (((c ^ (r & 7))) << 4);
        CP_ASYNC16(d, src, p);
    }
}

// ------------------------------ GEMM kernel ---------------------------------
// MODE 0: fp32 store (ldc)                                   [GEMM4 -> A]
// MODE 1: (acc+bias1)->C0/C1 hi/lo, (acc+bias2)->C2/C3 hi/lo [GEMM1]
// MODE 3: acc -> C0/C1 hi/lo                                 [GEMM2, GEMM3]
// MODE 2: (acc + Apos[m, clip(m-n)+mr]) * scale -> C0        [GEMM5, batched]
// TERMS 3: ah*bh + ah*bl + al*bh.  TERMS 2: ah*bh + al*bh (Bl never touched).
template <int MODE, bool BCHK, int TERMS>
__global__ __launch_bounds__(256, 1)
void tc_gemm(const __half* __restrict__ gAh, const __half* __restrict__ gAl,
             const __half* __restrict__ gBh, const __half* __restrict__ gBl,
             void* C0, void* C1, void* C2, void* C3,
             const float* __restrict__ bias1, const float* __restrict__ bias2,
             const float* __restrict__ Apos,
             int M, int N, int ld, int ldc, int rowOffA, int rowOffB,
             long long sC, long long sP, int maxrel, int ldp, float scale, int nk)
{
    extern __shared__ __align__(128) char smem_raw[];
    const uint32_t sb = smem_u32(smem_raw);
    const int tid = threadIdx.x, lane = tid & 31, wid = tid >> 5;
    const int bm = blockIdx.y * 128, bn = blockIdx.x * 128, bz = blockIdx.z;
    const int wm = wid >> 2, wn = wid & 3;            // warp grid 2 x 4
    const int rA = bz * rowOffA + bm;
    const int rB = bz * rowOffB + bn;

    float acc[4][4][4];
#pragma unroll
    for (int mi = 0; mi < 4; mi++)
#pragma unroll
        for (int ni = 0; ni < 4; ni++)
#pragma unroll
            for (int q = 0; q < 4; q++) acc[mi][ni][q] = 0.f;

    auto load_stage = [&](int s, int t) {
        const uint32_t base = sb + s * STAGE_B;
        const int k0 = t * 64;
        load_tile(base + 0 * TILE_B, gAh, rA, M, k0, ld, tid, BCHK);
        load_tile(base + 1 * TILE_B, gAl, rA, M, k0, ld, tid, BCHK);
        load_tile(base + 2 * TILE_B, gBh, rB, N, k0, ld, tid, BCHK);
        if (TERMS == 3)
            load_tile(base + 3 * TILE_B, gBl, rB, N, k0, ld, tid, BCHK);
    };

    load_stage(0, 0); CP_COMMIT();
    load_stage(1, 1); CP_COMMIT();

    // ldmatrix source addresses (lane-invariant parts)
    const int a_row = wm * 64 + (lane & 15);          // + mi*16
    const int a_cc  = lane >> 4;                      // + ks*2
    const int b_row = wn * 32 + (lane & 7);           // + ni*8
    const int b_cc  = (lane >> 3) & 1;                // + ks*2

    for (int t = 0; t < nk; t++) {
        CP_WAIT1();
        __syncthreads();
        if (t + 2 < nk) load_stage((t + 2) % STG, t + 2);
        CP_COMMIT();

        const uint32_t base = sb + (t % STG) * STAGE_B;
        const uint32_t sAh = base, sAl = base + TILE_B;
        const uint32_t sBh = base + 2 * TILE_B, sBl = base + 3 * TILE_B;

#pragma unroll
        for (int ks = 0; ks < 4; ks++) {
            uint32_t fAh[4][4], fAl[4][4], fBh[4][2], fBl[4][2];
#pragma unroll
            for (int mi = 0; mi < 4; mi++) {
                const int row = a_row + mi * 16;
                const int cc = ks * 2 + a_cc;
                const uint32_t off = row * 128 + (((cc ^ (row & 7))) << 4);
                LDSM_X4(fAh[mi][0], fAh[mi][1], fAh[mi][2], fAh[mi][3], sAh + off);
                LDSM_X4(fAl[mi][0], fAl[mi][1], fAl[mi][2], fAl[mi][3], sAl + off);
            }
#pragma unroll
            for (int ni = 0; ni < 4; ni++) {
                const int row = b_row + ni * 8;
                const int cc = ks * 2 + b_cc;
                const uint32_t off = row * 128 + (((cc ^ (row & 7))) << 4);
                LDSM_X2(fBh[ni][0], fBh[ni][1], sBh + off);
                if (TERMS == 3) LDSM_X2(fBl[ni][0], fBl[ni][1], sBl + off);
            }
#pragma unroll
            for (int mi = 0; mi < 4; mi++)
#pragma unroll
                for (int ni = 0; ni < 4; ni++) MMA16816(acc[mi][ni], fAh[mi], fBh[ni]);
            if (TERMS == 3) {
#pragma unroll
                for (int mi = 0; mi < 4; mi++)
#pragma unroll
                    for (int ni = 0; ni < 4; ni++) MMA16816(acc[mi][ni], fAh[mi], fBl[ni]);
            }
#pragma unroll
            for (int mi = 0; mi < 4; mi++)
#pragma unroll
                for (int ni = 0; ni < 4; ni++) MMA16816(acc[mi][ni], fAl[mi], fBh[ni]);
        }
    }

    // ------------------------------ epilogue --------------------------------
    const int lr = lane >> 2, lc = (lane & 3) * 2;

#pragma unroll
    for (int mi = 0; mi < 4; mi++) {
#pragma unroll
        for (int ni = 0; ni < 4; ni++) {
            const float* cc = acc[mi][ni];
            const int n = bn + wn * 32 + ni * 8 + lc;
#pragma unroll
            for (int h = 0; h < 2; h++) {
                const int m = bm + wm * 64 + mi * 16 + lr + h * 8;
                const float v0 = cc[h * 2 + 0], v1 = cc[h * 2 + 1];
                if (MODE == 0) {
                    if (BCHK && m >= M) continue;
                    float* Cf = (float*)C0;
                    if (!BCHK || n + 1 < N) {
                        *reinterpret_cast<float2*>(Cf + (size_t)m * ldc + n) = make_float2(v0, v1);
                    } else if (n < N) {
                        Cf[(size_t)m * ldc + n] = v0;
                    }
                } else if (MODE == 3) {
                    if (BCHK && m >= M) continue;
                    __half* Ch = (__half*)C0;
                    __half* Cl = (__half*)C1;
                    __half h0, l0, h1, l1;
                    split2h(v0, h0, l0); split2h(v1, h1, l1);
                    const size_t o = (size_t)m * ldc + n;
                    *reinterpret_cast<__half2*>(Ch + o) = __halves2half2(h0, h1);
                    *reinterpret_cast<__half2*>(Cl + o) = __halves2half2(l0, l1);
                } else if (MODE == 1) {
                    __half* Uh = (__half*)C0;
                    __half* Ul = (__half*)C1;
                    __half* Vh = (__half*)C2;
                    __half* Vl = (__half*)C3;
                    const size_t o = (size_t)m * ldc + n;
                    __half h0, l0, h1, l1;
                    split2h(v0 + bias1[n], h0, l0); split2h(v1 + bias1[n + 1], h1, l1);
                    *reinterpret_cast<__half2*>(Uh + o) = __halves2half2(h0, h1);
                    *reinterpret_cast<__half2*>(Ul + o) = __halves2half2(l0, l1);
                    split2h(v0 + bias2[n], h0, l0); split2h(v1 + bias2[n + 1], h1, l1);
                    *reinterpret_cast<__half2*>(Vh + o) = __halves2half2(h0, h1);
                    *reinterpret_cast<__half2*>(Vl + o) = __halves2half2(l0, l1);
                } else { // MODE 2
                    const float* Ap = Apos + (size_t)bz * sP + (size_t)m * ldp + maxrel;
                    float* Ob = (float*)C0 + (size_t)bz * sC + (size_t)m * ldc;
                    int r0 = m - n;
                    r0 = r0 > maxrel ? maxrel : (r0 < -maxrel ? -maxrel : r0);
                    int r1 = m - (n + 1);
                    r1 = r1 > maxrel ? maxrel : (r1 < -maxrel ? -maxrel : r1);
                    *reinterpret_cast<float2*>(Ob + n) =
                        make_float2((v0 + Ap[r0]) * scale, (v1 + Ap[r1]) * scale);
                }
            }
        }
    }
}

// ------------------------------- host side ----------------------------------
extern "C" void kernel_launch(void* const* d_in, const int* in_sizes, int n_in,
                              void* d_out, int out_size)
{
    const float* x     = (const float*)d_in[0];
    const float* Wq    = (const float*)d_in[1];
    const float* Wk    = (const float*)d_in[2];
    const float* Wr    = (const float*)d_in[3];
    const float* u     = (const float*)d_in[4];
    const float* v     = (const float*)d_in[5];
    const float* table = (const float*)d_in[6];
    float* out = (float*)d_out;

    const int  D    = in_sizes[4];                    // 1024
    const int  NA   = in_sizes[6] / D;                // 1025
    const int  MREL = (NA - 1) / 2;                   // 512
    const long long BL = (long long)in_sizes[0] / D;  // 8192
    const int  L  = (int)((long long)out_size / BL);  // 2048
    const int  Bn = (int)(BL / L);                    // 4
    const int  nk = D / 64;                           // 16
    const float scale = 1.f / sqrtf((float)D);

    void *xh,*xl,*wqh,*wql,*wkh,*wkl,*wrh,*wrl,*tbh,*tbl;
    void *quh,*qul,*qvh,*qvl,*kh,*kl,*rh,*rl,*Aa;
    cudaGetSymbolAddress(&xh,  g_xh);  cudaGetSymbolAddress(&xl,  g_xl);
    cudaGetSymbolAddress(&wqh, g_wqh); cudaGetSymbolAddress(&wql, g_wql);
    cudaGetSymbolAddress(&wkh, g_wkh); cudaGetSymbolAddress(&wkl, g_wkl);
    cudaGetSymbolAddress(&wrh, g_wrh); cudaGetSymbolAddress(&wrl, g_wrl);
    cudaGetSymbolAddress(&tbh, g_tbh); cudaGetSymbolAddress(&tbl, g_tbl);
    cudaGetSymbolAddress(&quh, g_quh); cudaGetSymbolAddress(&qul, g_qul);
    cudaGetSymbolAddress(&qvh, g_qvh); cudaGetSymbolAddress(&qvl, g_qvl);
    cudaGetSymbolAddress(&kh,  g_kh);  cudaGetSymbolAddress(&kl,  g_kl);
    cudaGetSymbolAddress(&rh,  g_rh);  cudaGetSymbolAddress(&rl,  g_rl);
    cudaGetSymbolAddress(&Aa,  g_A);

    static bool attr_done = false;
    if (!attr_done) {
        cudaFuncSetAttribute(tc_gemm<1,false,3>, cudaFuncAttributeMaxDynamicSharedMemorySize, SMEM_REQ);
        cudaFuncSetAttribute(tc_gemm<3,false,2>, cudaFuncAttributeMaxDynamicSharedMemorySize, SMEM_REQ);
        cudaFuncSetAttribute(tc_gemm<3,true ,3>, cudaFuncAttributeMaxDynamicSharedMemorySize, SMEM_REQ);
        cudaFuncSetAttribute(tc_gemm<0,true ,2>, cudaFuncAttributeMaxDynamicSharedMemorySize, SMEM_REQ);
        cudaFuncSetAttribute(tc_gemm<2,false,2>, cudaFuncAttributeMaxDynamicSharedMemorySize, SMEM_REQ);
        attr_done = true;
    }

    // ---- fused split: one launch for x, Wq, Wk, Wr, table ----
    {
        const int T = 256;
        const int bx = (int)(BL * D / 4) / T;   // 8192
        const int bw = (D * D / 4) / T;         // 1024
        const int bt = (NA * D / 4) / T;        // 1025
        const int p0 = bx, p1 = p0 + bw, p2 = p1 + bw, p3 = p2 + bw;
        split5<<<p3 + bt, T>>>(x, Wq, Wk, Wr, table,
            (__half*)xh,  (__half*)xl,
            (__half*)wqh, (__half*)wql,
            (__half*)wkh, (__half*)wkl,
            (__half*)wrh, (__half*)wrl,
            (__half*)tbh, (__half*)tbl,
            p0, p1, p2, p3);
    }

    const dim3 blk(256);

    // 1) Qu/Qv = x@Wq^T + u/v  -> fp16 hi/lo (MODE 1, 3-term: chain-critical)
    tc_gemm<1,false,3><<<dim3(D/128, (int)(BL/128), 1), blk, SMEM_REQ>>>(
        (const __half*)xh, (const __half*)xl,
        (const __half*)wqh, (const __half*)wql,
        quh, qul, qvh, qvl, u, v, nullptr,
        (int)BL, D, D, D, 0, 0, 0, 0, 0, 0, 0.f, nk);

    // 2) K = x@Wk^T -> fp16 hi/lo (MODE 3, 2-term)
    tc_gemm<3,false,2><<<dim3(D/128, (int)(BL/128), 1), blk, SMEM_REQ>>>(
        (const __half*)xh, (const __half*)xl,
        (const __half*)wkh, (const __half*)wkl,
        kh, kl, nullptr, nullptr, nullptr, nullptr, nullptr,
        (int)BL, D, D, D, 0, 0, 0, 0, 0, 0, 0.f, nk);

    // 3) R = table@Wr^T -> fp16 hi/lo (MODE 3, 3-term, M bounds 1025)
    tc_gemm<3,true,3><<<dim3(D/128, SDIV(NA,128), 1), blk, SMEM_REQ>>>(
        (const __half*)tbh, (const __half*)tbl,
        (const __half*)wrh, (const __half*)wrl,
        rh, rl, nullptr, nullptr, nullptr, nullptr, nullptr,
        NA, D, D, D, 0, 0, 0, 0, 0, 0, 0.f, nk);

    // 4) A = Qv@R^T -> fp32, ldc=LDP (MODE 0, 2-term, N bounds 1025)
    tc_gemm<0,true,2><<<dim3(SDIV(NA,128), (int)(BL/128), 1), blk, SMEM_REQ>>>(
        (const __half*)qvh, (const __half*)qvl,
        (const __half*)rh, (const __half*)rl,
        Aa, nullptr, nullptr, nullptr, nullptr, nullptr, nullptr,
        (int)BL, NA, D, LDP, 0, 0, 0, 0, 0, 0, 0.f, nk);

    // 5) out = (Qu@K^T + gather(A)) * scale, batched over B (MODE 2, 2-term)
    tc_gemm<2,false,2><<<dim3(L/128, L/128, Bn), blk, SMEM_REQ>>>(
        (const __half*)quh, (const __half*)qul,
        (const __half*)kh, (const __half*)kl,
        out, nullptr, nullptr, nullptr, nullptr, nullptr, (const float*)Aa,
        L, L, D, L, L, L,
        (long long)L * L, (long long)L * LDP, MREL, LDP, scale, nk);
}

// round 9
// speedup vs baseline: 1.4108x; 1.1002x over previous
#include <cuda_runtime.h>
#include <cuda_fp16.h>
#include <math.h>
#include <stdint.h>

// ---------------------------------------------------------------------------
// TransformerXL RPE via fp16 split-precision mma.sync GEMMs.
// out[b,i,j] = ( (Q+u)[b,i,:]·K[b,j,:] + A[b,i, clip(i-j)+M] ) / sqrt(D)
// Q = x@Wq^T, K = x@Wk^T, R = table@Wr^T, A = (Q+v)@R^T.
// A-side operands carried as fp16 hi+lo pairs (~22-bit), B-side rounded to
// fp16 hi only: a*b ~= ah*bh + al*bh (2-term on every GEMM).
// K and R are only ever B-side -> their lo halves are never materialized.
// Proven loop: CTA 128x128, warp 64x32, BK=64, 3-stage cp.async, 256 thr.
// ---------------------------------------------------------------------------

#define SDIV(a,b) (((a)+(b)-1)/(b))

static constexpr int STG      = 3;
static constexpr int TILE_B   = 128 * 128;        // 128 rows x 64 fp16 = 16 KB
static constexpr int STAGE_B  = 3 * TILE_B;       // Ah, Al, Bh
static constexpr int SMEM_REQ = STG * STAGE_B;    // 144 KB
static constexpr int LDP      = 1028;             // padded ld for A (pos) matrix

// ---------------- scratch (B=4, L=2048, D=1024, 2M+1=1025) -----------------
__device__ __align__(1024) __half g_xh [8192u*1024u];
__device__ __align__(1024) __half g_xl [8192u*1024u];
__device__ __align__(1024) __half g_wqh[1024u*1024u];
__device__ __align__(1024) __half g_wkh[1024u*1024u];
__device__ __align__(1024) __half g_wrh[1024u*1024u];
__device__ __align__(1024) __half g_tbh[1025u*1024u];
__device__ __align__(1024) __half g_tbl[1025u*1024u];
__device__ __align__(1024) __half g_quh[8192u*1024u];
__device__ __align__(1024) __half g_qul[8192u*1024u];
__device__ __align__(1024) __half g_qvh[8192u*1024u];
__device__ __align__(1024) __half g_qvl[8192u*1024u];
__device__ __align__(1024) __half g_kh [8192u*1024u];
__device__ __align__(1024) __half g_rh [1025u*1024u];
__device__ __align__(1024) float  g_A  [8192u*(unsigned)LDP];

// ---------------------------- PTX helpers ----------------------------------
__device__ __forceinline__ uint32_t smem_u32(const void* p) {
    uint32_t a;
    asm("{ .reg .u64 t; cvta.to.shared.u64 t, %1; cvt.u32.u64 %0, t; }" : "=r"(a) : "l"(p));
    return a;
}
#define CP_ASYNC16(dst, src, pbytes) \
    asm volatile("cp.async.cg.shared.global [%0], [%1], 16, %2;" \
                 :: "r"(dst), "l"(src), "r"(pbytes))
#define CP_COMMIT() asm volatile("cp.async.commit_group;" ::: "memory")
#define CP_WAIT1()  asm volatile("cp.async.wait_group 1;"  ::: "memory")

#define LDSM_X4(r0,r1,r2,r3,a) \
    asm volatile("ldmatrix.sync.aligned.m8n8.x4.shared.b16 {%0,%1,%2,%3}, [%4];" \
                 : "=r"(r0), "=r"(r1), "=r"(r2), "=r"(r3) : "r"(a))
#define LDSM_X2(r0,r1,a) \
    asm volatile("ldmatrix.sync.aligned.m8n8.x2.shared.b16 {%0,%1}, [%2];" \
                 : "=r"(r0), "=r"(r1) : "r"(a))
#define MMA16816(c, a, b) \
    asm volatile("mma.sync.aligned.m16n8k16.row.col.f32.f16.f16.f32 " \
                 "{%0,%1,%2,%3}, {%4,%5,%6,%7}, {%8,%9}, {%0,%1,%2,%3};" \
                 : "+f"((c)[0]), "+f"((c)[1]), "+f"((c)[2]), "+f"((c)[3]) \
                 : "r"((a)[0]), "r"((a)[1]), "r"((a)[2]), "r"((a)[3]), \
                   "r"((b)[0]), "r"((b)[1]))

__device__ __forceinline__ void split2h(float a, __half& h, __half& l) {
    h = __float2half_rn(a);
    l = __float2half_rn(a - __half2float(h));
}

// ------------------- fused split kernel (one launch, 5 segments) ------------
// x and table need hi+lo (A-side); Wq/Wk/Wr need hi only (B-side).
__global__ void split5(const float* __restrict__ i0, const float* __restrict__ i1,
                       const float* __restrict__ i2, const float* __restrict__ i3,
                       const float* __restrict__ i4,
                       __half* __restrict__ h0, __half* __restrict__ l0,
                       __half* __restrict__ h1,
                       __half* __restrict__ h2,
                       __half* __restrict__ h3,
                       __half* __restrict__ h4, __half* __restrict__ l4,
                       int p0, int p1, int p2, int p3)
{
    int b = blockIdx.x;
    const float* in; __half *hi, *lo = nullptr;
    if      (b < p0) { in = i0; hi = h0; lo = l0; }
    else if (b < p1) { in = i1; hi = h1; b -= p0; }
    else if (b < p2) { in = i2; hi = h2; b -= p1; }
    else if (b < p3) { in = i3; hi = h3; b -= p2; }
    else             { in = i4; hi = h4; lo = l4; b -= p3; }

    const int i = b * blockDim.x + threadIdx.x;
    float4 v = reinterpret_cast<const float4*>(in)[i];
    __half a0,b0,a1,b1,a2,b2,a3,b3;
    split2h(v.x,a0,b0); split2h(v.y,a1,b1); split2h(v.z,a2,b2); split2h(v.w,a3,b3);
    reinterpret_cast<__half2*>(hi)[i*2+0] = __halves2half2(a0,a1);
    reinterpret_cast<__half2*>(hi)[i*2+1] = __halves2half2(a2,a3);
    if (lo) {
        reinterpret_cast<__half2*>(lo)[i*2+0] = __halves2half2(b0,b1);
        reinterpret_cast<__half2*>(lo)[i*2+1] = __halves2half2(b2,b3);
    }
}

// ---------------------- tile loader (cp.async, swizzled) --------------------
// Tile: 128 rows x 64 fp16 (128 B rows). Chunk c (16 B) of row r stored at
// r*128 + ((c ^ (r&7))*16)  -> conflict-free for both cp.async and ldmatrix.
__device__ __forceinline__ void load_tile(uint32_t dst, const __half* g,
                                          int row0, int rows_max, int k0, int ld,
                                          int tid, bool bchk) {
#pragma unroll
    for (int i = 0; i < 4; i++) {
        const int idx = tid + i * 256;
        const int r = idx >> 3, c = idx & 7;
        int row = row0 + r;
        unsigned p = 16;
        if (bchk && row >= rows_max) { p = 0; row = 0; }
        const __half* src = g + (size_t)row * ld + k0 + c * 8;
        const uint32_t d = dst + r * 128 + (((c ^ (r & 7))) << 4);
        CP_ASYNC16(d, src, p);
    }
}

// ------------------------------ GEMM kernel ---------------------------------
// All GEMMs 2-term: acc = Ah*Bh + Al*Bh.
// MODE 0: fp32 store (ldc)                                   [GEMM4 -> A]
// MODE 1: (acc+bias1)->C0/C1 hi/lo, (acc+bias2)->C2/C3 hi/lo [GEMM1]
// MODE 4: acc -> C0 hi only                                  [GEMM2 K, GEMM3 R]
// MODE 2: (acc + Apos[m, clip(m-n)+mr]) * scale -> C0        [GEMM5, batched]
template <int MODE, bool BCHK>
__global__ __launch_bounds__(256, 1)
void tc_gemm(const __half* __restrict__ gAh, const __half* __restrict__ gAl,
             const __half* __restrict__ gBh,
             void* C0, void* C1, void* C2, void* C3,
             const float* __restrict__ bias1, const float* __restrict__ bias2,
             const float* __restrict__ Apos,
             int M, int N, int ld, int ldc, int rowOffA, int rowOffB,
             long long sC, long long sP, int maxrel, int ldp, float scale, int nk)
{
    extern __shared__ __align__(128) char smem_raw[];
    const uint32_t sb = smem_u32(smem_raw);
    const int tid = threadIdx.x, lane = tid & 31, wid = tid >> 5;
    const int bm = blockIdx.y * 128, bn = blockIdx.x * 128, bz = blockIdx.z;
    const int wm = wid >> 2, wn = wid & 3;            // warp grid 2 x 4
    const int rA = bz * rowOffA + bm;
    const int rB = bz * rowOffB + bn;

    float acc[4][4][4];
#pragma unroll
    for (int mi = 0; mi < 4; mi++)
#pragma unroll
        for (int ni = 0; ni < 4; ni++)
#pragma unroll
            for (int q = 0; q < 4; q++) acc[mi][ni][q] = 0.f;

    auto load_stage = [&](int s, int t) {
        const uint32_t base = sb + s * STAGE_B;
        const int k0 = t * 64;
        load_tile(base + 0 * TILE_B, gAh, rA, M, k0, ld, tid, BCHK);
        load_tile(base + 1 * TILE_B, gAl, rA, M, k0, ld, tid, BCHK);
        load_tile(base + 2 * TILE_B, gBh, rB, N, k0, ld, tid, BCHK);
    };

    load_stage(0, 0); CP_COMMIT();
    load_stage(1, 1); CP_COMMIT();

    // ldmatrix source addresses (lane-invariant parts)
    const int a_row = wm * 64 + (lane & 15);          // + mi*16
    const int a_cc  = lane >> 4;                      // + ks*2
    const int b_row = wn * 32 + (lane & 7);           // + ni*8
    const int b_cc  = (lane >> 3) & 1;                // + ks*2

    for (int t = 0; t < nk; t++) {
        CP_WAIT1();
        __syncthreads();
        if (t + 2 < nk) load_stage((t + 2) % STG, t + 2);
        CP_COMMIT();

        const uint32_t base = sb + (t % STG) * STAGE_B;
        const uint32_t sAh = base, sAl = base + TILE_B;
        const uint32_t sBh = base + 2 * TILE_B;

#pragma unroll
        for (int ks = 0; ks < 4; ks++) {
            uint32_t fAh[4][4], fAl[4][4], fBh[4][2];
#pragma unroll
            for (int mi = 0; mi < 4; mi++) {
                const int row = a_row + mi * 16;
                const int cc = ks * 2 + a_cc;
                const uint32_t off = row * 128 + (((cc ^ (row & 7))) << 4);
                LDSM_X4(fAh[mi][0], fAh[mi][1], fAh[mi][2], fAh[mi][3], sAh + off);
                LDSM_X4(fAl[mi][0], fAl[mi][1], fAl[mi][2], fAl[mi][3], sAl + off);
            }
#pragma unroll
            for (int ni = 0; ni < 4; ni++) {
                const int row = b_row + ni * 8;
                const int cc = ks * 2 + b_cc;
                const uint32_t off = row * 128 + (((cc ^ (row & 7))) << 4);
                LDSM_X2(fBh[ni][0], fBh[ni][1], sBh + off);
            }
#pragma unroll
            for (int mi = 0; mi < 4; mi++)
#pragma unroll
                for (int ni = 0; ni < 4; ni++) MMA16816(acc[mi][ni], fAh[mi], fBh[ni]);
#pragma unroll
            for (int mi = 0; mi < 4; mi++)
#pragma unroll
                for (int ni = 0; ni < 4; ni++) MMA16816(acc[mi][ni], fAl[mi], fBh[ni]);
        }
    }

    // ------------------------------ epilogue --------------------------------
    const int lr = lane >> 2, lc = (lane & 3) * 2;

#pragma unroll
    for (int mi = 0; mi < 4; mi++) {
#pragma unroll
        for (int ni = 0; ni < 4; ni++) {
            const float* cc = acc[mi][ni];
            const int n = bn + wn * 32 + ni * 8 + lc;
#pragma unroll
            for (int h = 0; h < 2; h++) {
                const int m = bm + wm * 64 + mi * 16 + lr + h * 8;
                const float v0 = cc[h * 2 + 0], v1 = cc[h * 2 + 1];
                if (MODE == 0) {
                    if (BCHK && m >= M) continue;
                    float* Cf = (float*)C0;
                    if (!BCHK || n + 1 < N) {
                        *reinterpret_cast<float2*>(Cf + (size_t)m * ldc + n) = make_float2(v0, v1);
                    } else if (n < N) {
                        Cf[(size_t)m * ldc + n] = v0;
                    }
                } else if (MODE == 4) {
                    if (BCHK && m >= M) continue;
                    __half* Ch = (__half*)C0;
                    *reinterpret_cast<__half2*>(Ch + (size_t)m * ldc + n) =
                        __halves2half2(__float2half_rn(v0), __float2half_rn(v1));
                } else if (MODE == 1) {
                    __half* Uh = (__half*)C0;
                    __half* Ul = (__half*)C1;
                    __half* Vh = (__half*)C2;
                    __half* Vl = (__half*)C3;
                    const size_t o = (size_t)m * ldc + n;
                    __half h0, l0, h1, l1;
                    split2h(v0 + bias1[n], h0, l0); split2h(v1 + bias1[n + 1], h1, l1);
                    *reinterpret_cast<__half2*>(Uh + o) = __halves2half2(h0, h1);
                    *reinterpret_cast<__half2*>(Ul + o) = __halves2half2(l0, l1);
                    split2h(v0 + bias2[n], h0, l0); split2h(v1 + bias2[n + 1], h1, l1);
                    *reinterpret_cast<__half2*>(Vh + o) = __halves2half2(h0, h1);
                    *reinterpret_cast<__half2*>(Vl + o) = __halves2half2(l0, l1);
                } else { // MODE 2
                    const float* Ap = Apos + (size_t)bz * sP + (size_t)m * ldp + maxrel;
                    float* Ob = (float*)C0 + (size_t)bz * sC + (size_t)m * ldc;
                    int r0 = m - n;
                    r0 = r0 > maxrel ? maxrel : (r0 < -maxrel ? -maxrel : r0);
                    int r1 = m - (n + 1);
                    r1 = r1 > maxrel ? maxrel : (r1 < -maxrel ? -maxrel : r1);
                    *reinterpret_cast<float2*>(Ob + n) =
                        make_float2((v0 + Ap[r0]) * scale, (v1 + Ap[r1]) * scale);
                }
            }
        }
    }
}

// ------------------------------- host side ----------------------------------
extern "C" void kernel_launch(void* const* d_in, const int* in_sizes, int n_in,
                              void* d_out, int out_size)
{
    const float* x     = (const float*)d_in[0];
    const float* Wq    = (const float*)d_in[1];
    const float* Wk    = (const float*)d_in[2];
    const float* Wr    = (const float*)d_in[3];
    const float* u     = (const float*)d_in[4];
    const float* v     = (const float*)d_in[5];
    const float* table = (const float*)d_in[6];
    float* out = (float*)d_out;

    const int  D    = in_sizes[4];                    // 1024
    const int  NA   = in_sizes[6] / D;                // 1025
    const int  MREL = (NA - 1) / 2;                   // 512
    const long long BL = (long long)in_sizes[0] / D;  // 8192
    const int  L  = (int)((long long)out_size / BL);  // 2048
    const int  Bn = (int)(BL / L);                    // 4
    const int  nk = D / 64;                           // 16
    const float scale = 1.f / sqrtf((float)D);

    void *xh,*xl,*wqh,*wkh,*wrh,*tbh,*tbl;
    void *quh,*qul,*qvh,*qvl,*kh,*rh,*Aa;
    cudaGetSymbolAddress(&xh,  g_xh);  cudaGetSymbolAddress(&xl,  g_xl);
    cudaGetSymbolAddress(&wqh, g_wqh);
    cudaGetSymbolAddress(&wkh, g_wkh);
    cudaGetSymbolAddress(&wrh, g_wrh);
    cudaGetSymbolAddress(&tbh, g_tbh); cudaGetSymbolAddress(&tbl, g_tbl);
    cudaGetSymbolAddress(&quh, g_quh); cudaGetSymbolAddress(&qul, g_qul);
    cudaGetSymbolAddress(&qvh, g_qvh); cudaGetSymbolAddress(&qvl, g_qvl);
    cudaGetSymbolAddress(&kh,  g_kh);
    cudaGetSymbolAddress(&rh,  g_rh);
    cudaGetSymbolAddress(&Aa,  g_A);

    static bool attr_done = false;
    if (!attr_done) {
        cudaFuncSetAttribute(tc_gemm<1,false>, cudaFuncAttributeMaxDynamicSharedMemorySize, SMEM_REQ);
        cudaFuncSetAttribute(tc_gemm<4,false>, cudaFuncAttributeMaxDynamicSharedMemorySize, SMEM_REQ);
        cudaFuncSetAttribute(tc_gemm<4,true >, cudaFuncAttributeMaxDynamicSharedMemorySize, SMEM_REQ);
        cudaFuncSetAttribute(tc_gemm<0,true >, cudaFuncAttributeMaxDynamicSharedMemorySize, SMEM_REQ);
        cudaFuncSetAttribute(tc_gemm<2,false>, cudaFuncAttributeMaxDynamicSharedMemorySize, SMEM_REQ);
        attr_done = true;
    }

    // ---- fused split: one launch for x(h+l), Wq(h), Wk(h), Wr(h), table(h+l) ----
    {
        const int T = 256;
        const int bx = (int)(BL * D / 4) / T;   // 8192
        const int bw = (D * D / 4) / T;         // 1024
        const int bt = (NA * D / 4) / T;        // 1025
        const int p0 = bx, p1 = p0 + bw, p2 = p1 + bw, p3 = p2 + bw;
        split5<<<p3 + bt, T>>>(x, Wq, Wk, Wr, table,
            (__half*)xh,  (__half*)xl,
            (__half*)wqh,
            (__half*)wkh,
            (__half*)wrh,
            (__half*)tbh, (__half*)tbl,
            p0, p1, p2, p3);
    }

    const dim3 blk(256);

    // 1) Qu/Qv = x@Wq^T + u/v  -> fp16 hi/lo (MODE 1)
    tc_gemm<1,false><<<dim3(D/128, (int)(BL/128), 1), blk, SMEM_REQ>>>(
        (const __half*)xh, (const __half*)xl, (const __half*)wqh,
        quh, qul, qvh, qvl, u, v, nullptr,
        (int)BL, D, D, D, 0, 0, 0, 0, 0, 0, 0.f, nk);

    // 2) K = x@Wk^T -> fp16 hi only (MODE 4)
    tc_gemm<4,false><<<dim3(D/128, (int)(BL/128), 1), blk, SMEM_REQ>>>(
        (const __half*)xh, (const __half*)xl, (const __half*)wkh,
        kh, nullptr, nullptr, nullptr, nullptr, nullptr, nullptr,
        (int)BL, D, D, D, 0, 0, 0, 0, 0, 0, 0.f, nk);

    // 3) R = table@Wr^T -> fp16 hi only (MODE 4, M bounds 1025)
    tc_gemm<4,true><<<dim3(D/128, SDIV(NA,128), 1), blk, SMEM_REQ>>>(
        (const __half*)tbh, (const __half*)tbl, (const __half*)wrh,
        rh, nullptr, nullptr, nullptr, nullptr, nullptr, nullptr,
        NA, D, D, D, 0, 0, 0, 0, 0, 0, 0.f, nk);

    // 4) A = Qv@R^T -> fp32, ldc=LDP (MODE 0, N bounds 1025)
    tc_gemm<0,true><<<dim3(SDIV(NA,128), (int)(BL/128), 1), blk, SMEM_REQ>>>(
        (const __half*)qvh, (const __half*)qvl, (const __half*)rh,
        Aa, nullptr, nullptr, nullptr, nullptr, nullptr, nullptr,
        (int)BL, NA, D, LDP, 0, 0, 0, 0, 0, 0, 0.f, nk);

    // 5) out = (Qu@K^T + gather(A)) * scale, batched over B (MODE 2)
    tc_gemm<2,false><<<dim3(L/128, L/128, Bn), blk, SMEM_REQ>>>(
        (const __half*)quh, (const __half*)qul, (const __half*)kh,
        out, nullptr, nullptr, nullptr, nullptr, nullptr, (const float*)Aa,
        L, L, D, L, L, L,
        (long long)L * L, (long long)L * LDP, MREL, LDP, scale, nk);
}

// round 10
// speedup vs baseline: 1.7508x; 1.2409x over previous
#include <cuda_runtime.h>
#include <cuda_fp16.h>
#include <math.h>
#include <stdint.h>

// ---------------------------------------------------------------------------
// TransformerXL RPE via fp16 split-precision mma.sync GEMMs.
// out[b,i,j] = ( (Q+u)[b,i,:]·K[b,j,:] + A[b,i, clip(i-j)+M] ) / sqrt(D)
// Q = x@Wq^T, K = x@Wk^T, R = table@Wr^T, A = (Q+v)@R^T.
// TERMS=2 GEMMs (G1 Q, G4 A): acc = (Ah+Al)*Bh  (A-side ~22-bit)
// TERMS=1 GEMMs (G2 K, G3 R, G5 content): pure fp16  acc = Ah*Bh
//   (K/R outputs are fp16-rounded anyway; content tolerates one more source)
// Proven loop: CTA 128x128, warp 64x32, BK=64, 3-stage cp.async, 256 thr.
// ---------------------------------------------------------------------------

#define SDIV(a,b) (((a)+(b)-1)/(b))

static constexpr int STG     = 3;
static constexpr int TILE_B  = 128 * 128;         // 128 rows x 64 fp16 = 16 KB
static constexpr int LDP     = 1028;              // padded ld for A (pos) matrix

// ---------------- scratch (B=4, L=2048, D=1024, 2M+1=1025) -----------------
__device__ __align__(1024) __half g_xh [8192u*1024u];
__device__ __align__(1024) __half g_xl [8192u*1024u];
__device__ __align__(1024) __half g_wqh[1024u*1024u];
__device__ __align__(1024) __half g_wkh[1024u*1024u];
__device__ __align__(1024) __half g_wrh[1024u*1024u];
__device__ __align__(1024) __half g_tbh[1025u*1024u];
__device__ __align__(1024) __half g_tbl[1025u*1024u];
__device__ __align__(1024) __half g_quh[8192u*1024u];
__device__ __align__(1024) __half g_qvh[8192u*1024u];
__device__ __align__(1024) __half g_qvl[8192u*1024u];
__device__ __align__(1024) __half g_kh [8192u*1024u];
__device__ __align__(1024) __half g_rh [1025u*1024u];
__device__ __align__(1024) float  g_A  [8192u*(unsigned)LDP];

// ---------------------------- PTX helpers ----------------------------------
__device__ __forceinline__ uint32_t smem_u32(const void* p) {
    uint32_t a;
    asm("{ .reg .u64 t; cvta.to.shared.u64 t, %1; cvt.u32.u64 %0, t; }" : "=r"(a) : "l"(p));
    return a;
}
#define CP_ASYNC16(dst, src, pbytes) \
    asm volatile("cp.async.cg.shared.global [%0], [%1], 16, %2;" \
                 :: "r"(dst), "l"(src), "r"(pbytes))
#define CP_COMMIT() asm volatile("cp.async.commit_group;" ::: "memory")
#define CP_WAIT1()  asm volatile("cp.async.wait_group 1;"  ::: "memory")

#define LDSM_X4(r0,r1,r2,r3,a) \
    asm volatile("ldmatrix.sync.aligned.m8n8.x4.shared.b16 {%0,%1,%2,%3}, [%4];" \
                 : "=r"(r0), "=r"(r1), "=r"(r2), "=r"(r3) : "r"(a))
#define LDSM_X2(r0,r1,a) \
    asm volatile("ldmatrix.sync.aligned.m8n8.x2.shared.b16 {%0,%1}, [%2];" \
                 : "=r"(r0), "=r"(r1) : "r"(a))
#define MMA16816(c, a, b) \
    asm volatile("mma.sync.aligned.m16n8k16.row.col.f32.f16.f16.f32 " \
                 "{%0,%1,%2,%3}, {%4,%5,%6,%7}, {%8,%9}, {%0,%1,%2,%3};" \
                 : "+f"((c)[0]), "+f"((c)[1]), "+f"((c)[2]), "+f"((c)[3]) \
                 : "r"((a)[0]), "r"((a)[1]), "r"((a)[2]), "r"((a)[3]), \
                   "r"((b)[0]), "r"((b)[1]))

__device__ __forceinline__ void split2h(float a, __half& h, __half& l) {
    h = __float2half_rn(a);
    l = __float2half_rn(a - __half2float(h));
}

// ------------------- fused split kernel (one launch, 5 segments) ------------
// x and table need hi+lo (A-side of 2-term GEMMs); Wq/Wk/Wr need hi only.
__global__ void split5(const float* __restrict__ i0, const float* __restrict__ i1,
                       const float* __restrict__ i2, const float* __restrict__ i3,
                       const float* __restrict__ i4,
                       __half* __restrict__ h0, __half* __restrict__ l0,
                       __half* __restrict__ h1,
                       __half* __restrict__ h2,
                       __half* __restrict__ h3,
                       __half* __restrict__ h4, __half* __restrict__ l4,
                       int p0, int p1, int p2, int p3)
{
    int b = blockIdx.x;
    const float* in; __half *hi, *lo = nullptr;
    if      (b < p0) { in = i0; hi = h0; lo = l0; }
    else if (b < p1) { in = i1; hi = h1; b -= p0; }
    else if (b < p2) { in = i2; hi = h2; b -= p1; }
    else if (b < p3) { in = i3; hi = h3; b -= p2; }
    else             { in = i4; hi = h4; lo = l4; b -= p3; }

    const int i = b * blockDim.x + threadIdx.x;
    float4 v = reinterpret_cast<const float4*>(in)[i];
    __half a0,b0,a1,b1,a2,b2,a3,b3;
    split2h(v.x,a0,b0); split2h(v.y,a1,b1); split2h(v.z,a2,b2); split2h(v.w,a3,b3);
    reinterpret_cast<__half2*>(hi)[i*2+0] = __halves2half2(a0,a1);
    reinterpret_cast<__half2*>(hi)[i*2+1] = __halves2half2(a2,a3);
    if (lo) {
        reinterpret_cast<__half2*>(lo)[i*2+0] = __halves2half2(b0,b1);
        reinterpret_cast<__half2*>(lo)[i*2+1] = __halves2half2(b2,b3);
    }
}

// ---------------------- tile loader (cp.async, swizzled) --------------------
// Tile: 128 rows x 64 fp16 (128 B rows). Chunk c (16 B) of row r stored at
// r*128 + ((c ^ (r&7))*16)  -> conflict-free for both cp.async and ldmatrix.
__device__ __forceinline__ void load_tile(uint32_t dst, const __half* g,
                                          int row0, int rows_max, int k0, int ld,
                                          int tid, bool bchk) {
#pragma unroll
    for (int i = 0; i < 4; i++) {
        const int idx = tid + i * 256;
        const int r = idx >> 3, c = idx & 7;
        int row = row0 + r;
        unsigned p = 16;
        if (bchk && row >= rows_max) { p = 0; row = 0; }
        const __half* src = g + (size_t)row * ld + k0 + c * 8;
        const uint32_t d = dst + r * 128 + (((c ^ (r & 7))) << 4);
        CP_ASYNC16(d, src, p);
    }
}

// ------------------------------ GEMM kernel ---------------------------------
// TERMS=2: acc = Ah*Bh + Al*Bh.   TERMS=1: acc = Ah*Bh (no Al tile at all).
// MODE 0: fp32 store (ldc)                                   [GEMM4 -> A]
// MODE 1: (acc+bias1)->C0 hi, (acc+bias2)->C2/C3 hi/lo       [GEMM1]
// MODE 4: acc -> C0 hi only                                  [GEMM2 K, GEMM3 R]
// MODE 2: (acc + Apos[m, clip(m-n)+mr]) * scale -> C0        [GEMM5, batched]
template <int MODE, bool BCHK, int TERMS>
__global__ __launch_bounds__(256, 1)
void tc_gemm(const __half* __restrict__ gAh, const __half* __restrict__ gAl,
             const __half* __restrict__ gBh,
             void* C0, void* C1, void* C2, void* C3,
             const float* __restrict__ bias1, const float* __restrict__ bias2,
             const float* __restrict__ Apos,
             int M, int N, int ld, int ldc, int rowOffA, int rowOffB,
             long long sC, long long sP, int maxrel, int ldp, float scale, int nk)
{
    constexpr int STAGE_B = (TERMS + 1) * TILE_B;   // Ah[,Al],Bh
    extern __shared__ __align__(128) char smem_raw[];
    const uint32_t sb = smem_u32(smem_raw);
    const int tid = threadIdx.x, lane = tid & 31, wid = tid >> 5;
    const int bm = blockIdx.y * 128, bn = blockIdx.x * 128, bz = blockIdx.z;
    const int wm = wid >> 2, wn = wid & 3;            // warp grid 2 x 4
    const int rA = bz * rowOffA + bm;
    const int rB = bz * rowOffB + bn;

    float acc[4][4][4];
#pragma unroll
    for (int mi = 0; mi < 4; mi++)
#pragma unroll
        for (int ni = 0; ni < 4; ni++)
#pragma unroll
            for (int q = 0; q < 4; q++) acc[mi][ni][q] = 0.f;

    auto load_stage = [&](int s, int t) {
        const uint32_t base = sb + s * STAGE_B;
        const int k0 = t * 64;
        load_tile(base, gAh, rA, M, k0, ld, tid, BCHK);
        if (TERMS == 2)
            load_tile(base + TILE_B, gAl, rA, M, k0, ld, tid, BCHK);
        load_tile(base + TERMS * TILE_B, gBh, rB, N, k0, ld, tid, BCHK);
    };

    load_stage(0, 0); CP_COMMIT();
    load_stage(1, 1); CP_COMMIT();

    // ldmatrix source addresses (lane-invariant parts)
    const int a_row = wm * 64 + (lane & 15);          // + mi*16
    const int a_cc  = lane >> 4;                      // + ks*2
    const int b_row = wn * 32 + (lane & 7);           // + ni*8
    const int b_cc  = (lane >> 3) & 1;                // + ks*2

    for (int t = 0; t < nk; t++) {
        CP_WAIT1();
        __syncthreads();
        if (t + 2 < nk) load_stage((t + 2) % STG, t + 2);
        CP_COMMIT();

        const uint32_t base = sb + (t % STG) * STAGE_B;
        const uint32_t sAh = base, sAl = base + TILE_B;
        const uint32_t sBh = base + TERMS * TILE_B;

#pragma unroll
        for (int ks = 0; ks < 4; ks++) {
            uint32_t fAh[4][4], fAl[4][4], fBh[4][2];
#pragma unroll
            for (int mi = 0; mi < 4; mi++) {
                const int row = a_row + mi * 16;
                const int cc = ks * 2 + a_cc;
                const uint32_t off = row * 128 + (((cc ^ (row & 7))) << 4);
                LDSM_X4(fAh[mi][0], fAh[mi][1], fAh[mi][2], fAh[mi][3], sAh + off);
                if (TERMS == 2)
                    LDSM_X4(fAl[mi][0], fAl[mi][1], fAl[mi][2], fAl[mi][3], sAl + off);
            }
#pragma unroll
            for (int ni = 0; ni < 4; ni++) {
                const int row = b_row + ni * 8;
                const int cc = ks * 2 + b_cc;
                const uint32_t off = row * 128 + (((cc ^ (row & 7))) << 4);
                LDSM_X2(fBh[ni][0], fBh[ni][1], sBh + off);
            }
#pragma unroll
            for (int mi = 0; mi < 4; mi++)
#pragma unroll
                for (int ni = 0; ni < 4; ni++) MMA16816(acc[mi][ni], fAh[mi], fBh[ni]);
            if (TERMS == 2) {
#pragma unroll
                for (int mi = 0; mi < 4; mi++)
#pragma unroll
                    for (int ni = 0; ni < 4; ni++) MMA16816(acc[mi][ni], fAl[mi], fBh[ni]);
            }
        }
    }

    // ------------------------------ epilogue --------------------------------
    const int lr = lane >> 2, lc = (lane & 3) * 2;

#pragma unroll
    for (int mi = 0; mi < 4; mi++) {
#pragma unroll
        for (int ni = 0; ni < 4; ni++) {
            const float* cc = acc[mi][ni];
            const int n = bn + wn * 32 + ni * 8 + lc;
#pragma unroll
            for (int h = 0; h < 2; h++) {
                const int m = bm + wm * 64 + mi * 16 + lr + h * 8;
                const float v0 = cc[h * 2 + 0], v1 = cc[h * 2 + 1];
                if (MODE == 0) {
                    if (BCHK && m >= M) continue;
                    float* Cf = (float*)C0;
                    if (!BCHK || n + 1 < N) {
                        *reinterpret_cast<float2*>(Cf + (size_t)m * ldc + n) = make_float2(v0, v1);
                    } else if (n < N) {
                        Cf[(size_t)m * ldc + n] = v0;
                    }
                } else if (MODE == 4) {
                    if (BCHK && m >= M) continue;
                    __half* Ch = (__half*)C0;
                    *reinterpret_cast<__half2*>(Ch + (size_t)m * ldc + n) =
                        __halves2half2(__float2half_rn(v0), __float2half_rn(v1));
                } else if (MODE == 1) {
                    __half* Uh = (__half*)C0;
                    __half* Vh = (__half*)C2;
                    __half* Vl = (__half*)C3;
                    const size_t o = (size_t)m * ldc + n;
                    *reinterpret_cast<__half2*>(Uh + o) =
                        __halves2half2(__float2half_rn(v0 + bias1[n]),
                                       __float2half_rn(v1 + bias1[n + 1]));
                    __half h0, l0, h1, l1;
                    split2h(v0 + bias2[n], h0, l0); split2h(v1 + bias2[n + 1], h1, l1);
                    *reinterpret_cast<__half2*>(Vh + o) = __halves2half2(h0, h1);
                    *reinterpret_cast<__half2*>(Vl + o) = __halves2half2(l0, l1);
                } else { // MODE 2
                    const float* Ap = Apos + (size_t)bz * sP + (size_t)m * ldp + maxrel;
                    float* Ob = (float*)C0 + (size_t)bz * sC + (size_t)m * ldc;
                    int r0 = m - n;
                    r0 = r0 > maxrel ? maxrel : (r0 < -maxrel ? -maxrel : r0);
                    int r1 = m - (n + 1);
                    r1 = r1 > maxrel ? maxrel : (r1 < -maxrel ? -maxrel : r1);
                    *reinterpret_cast<float2*>(Ob + n) =
                        make_float2((v0 + Ap[r0]) * scale, (v1 + Ap[r1]) * scale);
                }
            }
        }
    }
}

// ------------------------------- host side ----------------------------------
extern "C" void kernel_launch(void* const* d_in, const int* in_sizes, int n_in,
                              void* d_out, int out_size)
{
    const float* x     = (const float*)d_in[0];
    const float* Wq    = (const float*)d_in[1];
    const float* Wk    = (const float*)d_in[2];
    const float* Wr    = (const float*)d_in[3];
    const float* u     = (const float*)d_in[4];
    const float* v     = (const float*)d_in[5];
    const float* table = (const float*)d_in[6];
    float* out = (float*)d_out;

    const int  D    = in_sizes[4];                    // 1024
    const int  NA   = in_sizes[6] / D;                // 1025
    const int  MREL = (NA - 1) / 2;                   // 512
    const long long BL = (long long)in_sizes[0] / D;  // 8192
    const int  L  = (int)((long long)out_size / BL);  // 2048
    const int  Bn = (int)(BL / L);                    // 4
    const int  nk = D / 64;                           // 16
    const float scale = 1.f / sqrtf((float)D);

    const int SMEM2 = STG * 3 * TILE_B;               // 144 KB (TERMS=2)
    const int SMEM1 = STG * 2 * TILE_B;               //  96 KB (TERMS=1)

    void *xh,*xl,*wqh,*wkh,*wrh,*tbh,*tbl;
    void *quh,*qvh,*qvl,*kh,*rh,*Aa;
    cudaGetSymbolAddress(&xh,  g_xh);  cudaGetSymbolAddress(&xl,  g_xl);
    cudaGetSymbolAddress(&wqh, g_wqh);
    cudaGetSymbolAddress(&wkh, g_wkh);
    cudaGetSymbolAddress(&wrh, g_wrh);
    cudaGetSymbolAddress(&tbh, g_tbh); cudaGetSymbolAddress(&tbl, g_tbl);
    cudaGetSymbolAddress(&quh, g_quh);
    cudaGetSymbolAddress(&qvh, g_qvh); cudaGetSymbolAddress(&qvl, g_qvl);
    cudaGetSymbolAddress(&kh,  g_kh);
    cudaGetSymbolAddress(&rh,  g_rh);
    cudaGetSymbolAddress(&Aa,  g_A);

    static bool attr_done = false;
    if (!attr_done) {
        cudaFuncSetAttribute(tc_gemm<1,false,2>, cudaFuncAttributeMaxDynamicSharedMemorySize, SMEM2);
        cudaFuncSetAttribute(tc_gemm<4,false,1>, cudaFuncAttributeMaxDynamicSharedMemorySize, SMEM1);
        cudaFuncSetAttribute(tc_gemm<4,true ,1>, cudaFuncAttributeMaxDynamicSharedMemorySize, SMEM1);
        cudaFuncSetAttribute(tc_gemm<0,true ,2>, cudaFuncAttributeMaxDynamicSharedMemorySize, SMEM2);
        cudaFuncSetAttribute(tc_gemm<2,false,1>, cudaFuncAttributeMaxDynamicSharedMemorySize, SMEM1);
        attr_done = true;
    }

    // ---- fused split: one launch for x(h+l), Wq(h), Wk(h), Wr(h), table(h+l) ----
    {
        const int T = 256;
        const int bx = (int)(BL * D / 4) / T;   // 8192
        const int bw = (D * D / 4) / T;         // 1024
        const int bt = (NA * D / 4) / T;        // 1025
        const int p0 = bx, p1 = p0 + bw, p2 = p1 + bw, p3 = p2 + bw;
        split5<<<p3 + bt, T>>>(x, Wq, Wk, Wr, table,
            (__half*)xh,  (__half*)xl,
            (__half*)wqh,
            (__half*)wkh,
            (__half*)wrh,
            (__half*)tbh, (__half*)tbl,
            p0, p1, p2, p3);
    }

    const dim3 blk(256);

    // 1) Qu/Qv = x@Wq^T + u/v  (TERMS=2; Qu hi, Qv hi/lo)
    tc_gemm<1,false,2><<<dim3(D/128, (int)(BL/128), 1), blk, SMEM2>>>(
        (const __half*)xh, (const __half*)xl, (const __half*)wqh,
        quh, nullptr, qvh, qvl, u, v, nullptr,
        (int)BL, D, D, D, 0, 0, 0, 0, 0, 0, 0.f, nk);

    // 2) K = xh@Wk^T -> fp16 hi (TERMS=1)
    tc_gemm<4,false,1><<<dim3(D/128, (int)(BL/128), 1), blk, SMEM1>>>(
        (const __half*)xh, nullptr, (const __half*)wkh,
        kh, nullptr, nullptr, nullptr, nullptr, nullptr, nullptr,
        (int)BL, D, D, D, 0, 0, 0, 0, 0, 0, 0.f, nk);

    // 3) R = tbh@Wr^T -> fp16 hi (TERMS=1, M bounds 1025)
    tc_gemm<4,true,1><<<dim3(D/128, SDIV(NA,128), 1), blk, SMEM1>>>(
        (const __half*)tbh, nullptr, (const __half*)wrh,
        rh, nullptr, nullptr, nullptr, nullptr, nullptr, nullptr,
        NA, D, D, D, 0, 0, 0, 0, 0, 0, 0.f, nk);

    // 4) A = Qv@R^T -> fp32, ldc=LDP (TERMS=2, N bounds 1025)
    tc_gemm<0,true,2><<<dim3(SDIV(NA,128), (int)(BL/128), 1), blk, SMEM2>>>(
        (const __half*)qvh, (const __half*)qvl, (const __half*)rh,
        Aa, nullptr, nullptr, nullptr, nullptr, nullptr, nullptr,
        (int)BL, NA, D, LDP, 0, 0, 0, 0, 0, 0, 0.f, nk);

    // 5) out = (Quh@K^T + gather(A)) * scale, batched over B (TERMS=1)
    tc_gemm<2,false,1><<<dim3(L/128, L/128, Bn), blk, SMEM1>>>(
        (const __half*)quh, nullptr, (const __half*)kh,
        out, nullptr, nullptr, nullptr, nullptr, nullptr, (const float*)Aa,
        L, L, D, L, L, L,
        (long long)L * L, (long long)L * LDP, MREL, LDP, scale, nk);
}

// round 11
// speedup vs baseline: 2.2893x; 1.3076x over previous
#include <cuda_runtime.h>
#include <cuda_fp16.h>
#include <math.h>
#include <stdint.h>

// ---------------------------------------------------------------------------
// TransformerXL RPE via pure-fp16 mma.sync GEMMs (fp32 accumulate).
// out[b,i,j] = ( (Q+u)[b,i,:]·K[b,j,:] + A[b,i, clip(i-j)+M] ) / sqrt(D)
// Q = x@Wq^T, K = x@Wk^T, R = table@Wr^T, A = (Q+v)@R^T.
// All operands rounded to fp16 (inputs once, intermediates at epilogues);
// every GEMM accumulates in fp32. ~6 independent 2^-12 rounding sources
// per output path -> rel_err ~5e-4 < 1e-3.
// Proven loop: CTA 128x128, warp 64x32, BK=64, 3-stage cp.async, 256 thr.
// ---------------------------------------------------------------------------

#define SDIV(a,b) (((a)+(b)-1)/(b))

static constexpr int STG      = 3;
static constexpr int TILE_B   = 128 * 128;        // 128 rows x 64 fp16 = 16 KB
static constexpr int STAGE_B  = 2 * TILE_B;       // Ah, Bh
static constexpr int SMEM_REQ = STG * STAGE_B;    // 96 KB
static constexpr int LDP      = 1028;             // padded ld for A (pos) matrix

// ---------------- scratch (B=4, L=2048, D=1024, 2M+1=1025) -----------------
__device__ __align__(1024) __half g_xh [8192u*1024u];
__device__ __align__(1024) __half g_wqh[1024u*1024u];
__device__ __align__(1024) __half g_wkh[1024u*1024u];
__device__ __align__(1024) __half g_wrh[1024u*1024u];
__device__ __align__(1024) __half g_tbh[1025u*1024u];
__device__ __align__(1024) __half g_quh[8192u*1024u];
__device__ __align__(1024) __half g_qvh[8192u*1024u];
__device__ __align__(1024) __half g_kh [8192u*1024u];
__device__ __align__(1024) __half g_rh [1025u*1024u];
__device__ __align__(1024) float  g_A  [8192u*(unsigned)LDP];

// ---------------------------- PTX helpers ----------------------------------
__device__ __forceinline__ uint32_t smem_u32(const void* p) {
    uint32_t a;
    asm("{ .reg .u64 t; cvta.to.shared.u64 t, %1; cvt.u32.u64 %0, t; }" : "=r"(a) : "l"(p));
    return a;
}
#define CP_ASYNC16(dst, src, pbytes) \
    asm volatile("cp.async.cg.shared.global [%0], [%1], 16, %2;" \
                 :: "r"(dst), "l"(src), "r"(pbytes))
#define CP_COMMIT() asm volatile("cp.async.commit_group;" ::: "memory")
#define CP_WAIT1()  asm volatile("cp.async.wait_group 1;"  ::: "memory")

#define LDSM_X4(r0,r1,r2,r3,a) \
    asm volatile("ldmatrix.sync.aligned.m8n8.x4.shared.b16 {%0,%1,%2,%3}, [%4];" \
                 : "=r"(r0), "=r"(r1), "=r"(r2), "=r"(r3) : "r"(a))
#define LDSM_X2(r0,r1,a) \
    asm volatile("ldmatrix.sync.aligned.m8n8.x2.shared.b16 {%0,%1}, [%2];" \
                 : "=r"(r0), "=r"(r1) : "r"(a))
#define MMA16816(c, a, b) \
    asm volatile("mma.sync.aligned.m16n8k16.row.col.f32.f16.f16.f32 " \
                 "{%0,%1,%2,%3}, {%4,%5,%6,%7}, {%8,%9}, {%0,%1,%2,%3};" \
                 : "+f"((c)[0]), "+f"((c)[1]), "+f"((c)[2]), "+f"((c)[3]) \
                 : "r"((a)[0]), "r"((a)[1]), "r"((a)[2]), "r"((a)[3]), \
                   "r"((b)[0]), "r"((b)[1]))

// ------------------- fused split kernel (one launch, 5 segments) ------------
// All inputs rounded to fp16 hi only.
__global__ void split5(const float* __restrict__ i0, const float* __restrict__ i1,
                       const float* __restrict__ i2, const float* __restrict__ i3,
                       const float* __restrict__ i4,
                       __half* __restrict__ h0, __half* __restrict__ h1,
                       __half* __restrict__ h2, __half* __restrict__ h3,
                       __half* __restrict__ h4,
                       int p0, int p1, int p2, int p3)
{
    int b = blockIdx.x;
    const float* in; __half* hi;
    if      (b < p0) { in = i0; hi = h0; }
    else if (b < p1) { in = i1; hi = h1; b -= p0; }
    else if (b < p2) { in = i2; hi = h2; b -= p1; }
    else if (b < p3) { in = i3; hi = h3; b -= p2; }
    else             { in = i4; hi = h4; b -= p3; }

    const int i = b * blockDim.x + threadIdx.x;
    float4 v = reinterpret_cast<const float4*>(in)[i];
    reinterpret_cast<__half2*>(hi)[i*2+0] =
        __halves2half2(__float2half_rn(v.x), __float2half_rn(v.y));
    reinterpret_cast<__half2*>(hi)[i*2+1] =
        __halves2half2(__float2half_rn(v.z), __float2half_rn(v.w));
}

// ---------------------- tile loader (cp.async, swizzled) --------------------
// Tile: 128 rows x 64 fp16 (128 B rows). Chunk c (16 B) of row r stored at
// r*128 + ((c ^ (r&7))*16)  -> conflict-free for both cp.async and ldmatrix.
__device__ __forceinline__ void load_tile(uint32_t dst, const __half* g,
                                          int row0, int rows_max, int k0, int ld,
                                          int tid, bool bchk) {
#pragma unroll
    for (int i = 0; i < 4; i++) {
        const int idx = tid + i * 256;
        const int r = idx >> 3, c = idx & 7;
        int row = row0 + r;
        unsigned p = 16;
        if (bchk && row >= rows_max) { p = 0; row = 0; }
        const __half* src = g + (size_t)row * ld + k0 + c * 8;
        const uint32_t d = dst + r * 128 + (((c ^ (r & 7))) << 4);
        CP_ASYNC16(d, src, p);
    }
}

// ------------------------------ GEMM kernel ---------------------------------
// acc = Ah * Bh (fp32 accumulate).
// MODE 0: fp32 store (ldc)                                   [GEMM4 -> A]
// MODE 1: (acc+bias1)->C0 fp16, (acc+bias2)->C1 fp16         [GEMM1 Qu/Qv]
// MODE 4: acc -> C0 fp16                                     [GEMM2 K, GEMM3 R]
// MODE 2: (acc + Apos[m, clip(m-n)+mr]) * scale -> C0        [GEMM5, batched]
template <int MODE, bool BCHK>
__global__ __launch_bounds__(256, 1)
void tc_gemm(const __half* __restrict__ gAh, const __half* __restrict__ gBh,
             void* C0, void* C1,
             const float* __restrict__ bias1, const float* __restrict__ bias2,
             const float* __restrict__ Apos,
             int M, int N, int ld, int ldc, int rowOffA, int rowOffB,
             long long sC, long long sP, int maxrel, int ldp, float scale, int nk)
{
    extern __shared__ __align__(128) char smem_raw[];
    const uint32_t sb = smem_u32(smem_raw);
    const int tid = threadIdx.x, lane = tid & 31, wid = tid >> 5;
    const int bm = blockIdx.y * 128, bn = blockIdx.x * 128, bz = blockIdx.z;
    const int wm = wid >> 2, wn = wid & 3;            // warp grid 2 x 4
    const int rA = bz * rowOffA + bm;
    const int rB = bz * rowOffB + bn;

    float acc[4][4][4];
#pragma unroll
    for (int mi = 0; mi < 4; mi++)
#pragma unroll
        for (int ni = 0; ni < 4; ni++)
#pragma unroll
            for (int q = 0; q < 4; q++) acc[mi][ni][q] = 0.f;

    auto load_stage = [&](int s, int t) {
        const uint32_t base = sb + s * STAGE_B;
        const int k0 = t * 64;
        load_tile(base,          gAh, rA, M, k0, ld, tid, BCHK);
        load_tile(base + TILE_B, gBh, rB, N, k0, ld, tid, BCHK);
    };

    load_stage(0, 0); CP_COMMIT();
    load_stage(1, 1); CP_COMMIT();

    // ldmatrix source addresses (lane-invariant parts)
    const int a_row = wm * 64 + (lane & 15);          // + mi*16
    const int a_cc  = lane >> 4;                      // + ks*2
    const int b_row = wn * 32 + (lane & 7);           // + ni*8
    const int b_cc  = (lane >> 3) & 1;                // + ks*2

    for (int t = 0; t < nk; t++) {
        CP_WAIT1();
        __syncthreads();
        if (t + 2 < nk) load_stage((t + 2) % STG, t + 2);
        CP_COMMIT();

        const uint32_t base = sb + (t % STG) * STAGE_B;
        const uint32_t sAh = base, sBh = base + TILE_B;

#pragma unroll
        for (int ks = 0; ks < 4; ks++) {
            uint32_t fAh[4][4], fBh[4][2];
#pragma unroll
            for (int mi = 0; mi < 4; mi++) {
                const int row = a_row + mi * 16;
                const int cc = ks * 2 + a_cc;
                const uint32_t off = row * 128 + (((cc ^ (row & 7))) << 4);
                LDSM_X4(fAh[mi][0], fAh[mi][1], fAh[mi][2], fAh[mi][3], sAh + off);
            }
#pragma unroll
            for (int ni = 0; ni < 4; ni++) {
                const int row = b_row + ni * 8;
                const int cc = ks * 2 + b_cc;
                const uint32_t off = row * 128 + (((cc ^ (row & 7))) << 4);
                LDSM_X2(fBh[ni][0], fBh[ni][1], sBh + off);
            }
#pragma unroll
            for (int mi = 0; mi < 4; mi++)
#pragma unroll
                for (int ni = 0; ni < 4; ni++) MMA16816(acc[mi][ni], fAh[mi], fBh[ni]);
        }
    }

    // ------------------------------ epilogue --------------------------------
    const int lr = lane >> 2, lc = (lane & 3) * 2;

#pragma unroll
    for (int mi = 0; mi < 4; mi++) {
#pragma unroll
        for (int ni = 0; ni < 4; ni++) {
            const float* cc = acc[mi][ni];
            const int n = bn + wn * 32 + ni * 8 + lc;
#pragma unroll
            for (int h = 0; h < 2; h++) {
                const int m = bm + wm * 64 + mi * 16 + lr + h * 8;
                const float v0 = cc[h * 2 + 0], v1 = cc[h * 2 + 1];
                if (MODE == 0) {
                    if (BCHK && m >= M) continue;
                    float* Cf = (float*)C0;
                    if (!BCHK || n + 1 < N) {
                        *reinterpret_cast<float2*>(Cf + (size_t)m * ldc + n) = make_float2(v0, v1);
                    } else if (n < N) {
                        Cf[(size_t)m * ldc + n] = v0;
                    }
                } else if (MODE == 4) {
                    if (BCHK && m >= M) continue;
                    __half* Ch = (__half*)C0;
                    *reinterpret_cast<__half2*>(Ch + (size_t)m * ldc + n) =
                        __halves2half2(__float2half_rn(v0), __float2half_rn(v1));
                } else if (MODE == 1) {
                    __half* Uh = (__half*)C0;
                    __half* Vh = (__half*)C1;
                    const size_t o = (size_t)m * ldc + n;
                    *reinterpret_cast<__half2*>(Uh + o) =
                        __halves2half2(__float2half_rn(v0 + bias1[n]),
                                       __float2half_rn(v1 + bias1[n + 1]));
                    *reinterpret_cast<__half2*>(Vh + o) =
                        __halves2half2(__float2half_rn(v0 + bias2[n]),
                                       __float2half_rn(v1 + bias2[n + 1]));
                } else { // MODE 2
                    const float* Ap = Apos + (size_t)bz * sP + (size_t)m * ldp + maxrel;
                    float* Ob = (float*)C0 + (size_t)bz * sC + (size_t)m * ldc;
                    int r0 = m - n;
                    r0 = r0 > maxrel ? maxrel : (r0 < -maxrel ? -maxrel : r0);
                    int r1 = m - (n + 1);
                    r1 = r1 > maxrel ? maxrel : (r1 < -maxrel ? -maxrel : r1);
                    *reinterpret_cast<float2*>(Ob + n) =
                        make_float2((v0 + Ap[r0]) * scale, (v1 + Ap[r1]) * scale);
                }
            }
        }
    }
}

// ------------------------------- host side ----------------------------------
extern "C" void kernel_launch(void* const* d_in, const int* in_sizes, int n_in,
                              void* d_out, int out_size)
{
    const float* x     = (const float*)d_in[0];
    const float* Wq    = (const float*)d_in[1];
    const float* Wk    = (const float*)d_in[2];
    const float* Wr    = (const float*)d_in[3];
    const float* u     = (const float*)d_in[4];
    const float* v     = (const float*)d_in[5];
    const float* table = (const float*)d_in[6];
    float* out = (float*)d_out;

    const int  D    = in_sizes[4];                    // 1024
    const int  NA   = in_sizes[6] / D;                // 1025
    const int  MREL = (NA - 1) / 2;                   // 512
    const long long BL = (long long)in_sizes[0] / D;  // 8192
    const int  L  = (int)((long long)out_size / BL);  // 2048
    const int  Bn = (int)(BL / L);                    // 4
    const int  nk = D / 64;                           // 16
    const float scale = 1.f / sqrtf((float)D);

    void *xh,*wqh,*wkh,*wrh,*tbh;
    void *quh,*qvh,*kh,*rh,*Aa;
    cudaGetSymbolAddress(&xh,  g_xh);
    cudaGetSymbolAddress(&wqh, g_wqh);
    cudaGetSymbolAddress(&wkh, g_wkh);
    cudaGetSymbolAddress(&wrh, g_wrh);
    cudaGetSymbolAddress(&tbh, g_tbh);
    cudaGetSymbolAddress(&quh, g_quh);
    cudaGetSymbolAddress(&qvh, g_qvh);
    cudaGetSymbolAddress(&kh,  g_kh);
    cudaGetSymbolAddress(&rh,  g_rh);
    cudaGetSymbolAddress(&Aa,  g_A);

    static bool attr_done = false;
    if (!attr_done) {
        cudaFuncSetAttribute(tc_gemm<1,false>, cudaFuncAttributeMaxDynamicSharedMemorySize, SMEM_REQ);
        cudaFuncSetAttribute(tc_gemm<4,false>, cudaFuncAttributeMaxDynamicSharedMemorySize, SMEM_REQ);
        cudaFuncSetAttribute(tc_gemm<4,true >, cudaFuncAttributeMaxDynamicSharedMemorySize, SMEM_REQ);
        cudaFuncSetAttribute(tc_gemm<0,true >, cudaFuncAttributeMaxDynamicSharedMemorySize, SMEM_REQ);
        cudaFuncSetAttribute(tc_gemm<2,false>, cudaFuncAttributeMaxDynamicSharedMemorySize, SMEM_REQ);
        attr_done = true;
    }

    // ---- fused split: one launch, fp16-round x, Wq, Wk, Wr, table ----
    {
        const int T = 256;
        const int bx = (int)(BL * D / 4) / T;   // 8192
        const int bw = (D * D / 4) / T;         // 1024
        const int bt = (NA * D / 4) / T;        // 1025
        const int p0 = bx, p1 = p0 + bw, p2 = p1 + bw, p3 = p2 + bw;
        split5<<<p3 + bt, T>>>(x, Wq, Wk, Wr, table,
            (__half*)xh, (__half*)wqh, (__half*)wkh, (__half*)wrh, (__half*)tbh,
            p0, p1, p2, p3);
    }

    const dim3 blk(256);

    // 1) Qu = round(x@Wq^T + u), Qv = round(x@Wq^T + v)  (MODE 1)
    tc_gemm<1,false><<<dim3(D/128, (int)(BL/128), 1), blk, SMEM_REQ>>>(
        (const __half*)xh, (const __half*)wqh,
        quh, qvh, u, v, nullptr,
        (int)BL, D, D, D, 0, 0, 0, 0, 0, 0, 0.f, nk);

    // 2) K = round(x@Wk^T)  (MODE 4)
    tc_gemm<4,false><<<dim3(D/128, (int)(BL/128), 1), blk, SMEM_REQ>>>(
        (const __half*)xh, (const __half*)wkh,
        kh, nullptr, nullptr, nullptr, nullptr,
        (int)BL, D, D, D, 0, 0, 0, 0, 0, 0, 0.f, nk);

    // 3) R = round(table@Wr^T)  (MODE 4, M bounds 1025)
    tc_gemm<4,true><<<dim3(D/128, SDIV(NA,128), 1), blk, SMEM_REQ>>>(
        (const __half*)tbh, (const __half*)wrh,
        rh, nullptr, nullptr, nullptr, nullptr,
        NA, D, D, D, 0, 0, 0, 0, 0, 0, 0.f, nk);

    // 4) A = Qv@R^T -> fp32, ldc=LDP  (MODE 0, N bounds 1025)
    tc_gemm<0,true><<<dim3(SDIV(NA,128), (int)(BL/128), 1), blk, SMEM_REQ>>>(
        (const __half*)qvh, (const __half*)rh,
        Aa, nullptr, nullptr, nullptr, nullptr,
        (int)BL, NA, D, LDP, 0, 0, 0, 0, 0, 0, 0.f, nk);

    // 5) out = (Qu@K^T + gather(A)) * scale, batched over B  (MODE 2)
    tc_gemm<2,false><<<dim3(L/128, L/128, Bn), blk, SMEM_REQ>>>(
        (const __half*)quh, (const __half*)kh,
        out, nullptr, nullptr, nullptr, (const float*)Aa,
        L, L, D, L, L, L,
        (long long)L * L, (long long)L * LDP, MREL, LDP, scale, nk);
}

// round 12
// speedup vs baseline: 2.5982x; 1.1349x over previous
#include <cuda_runtime.h>
#include <cuda_fp16.h>
#include <math.h>
#include <stdint.h>

// ---------------------------------------------------------------------------
// TransformerXL RPE via pure-fp16 mma.sync GEMMs (fp32 accumulate).
// out[b,i,j] = ( (Q+u)[b,i,:]·K[b,j,:] + A[b,i, clip(i-j)+M] ) / sqrt(D)
// Q = x@Wq^T, K = x@Wk^T, R = table@Wr^T, A = (Q+v)@R^T.
// All operands rounded to fp16; fp32 accumulate. rel_err ~4e-4 < 1e-3.
// Loop: CTA 128x128, warp 64x32, BK=64, 3-stage cp.async, 256 thr.
// NEW: __launch_bounds__(256,2) caps regs at 128 -> 2 CTAs/SM (96 KB smem
// each, 192 KB total). Independent CTAs interleave sync/load windows with
// MMA issue, filling the tensor-pipe bubbles a single CTA exposes.
// ---------------------------------------------------------------------------

#define SDIV(a,b) (((a)+(b)-1)/(b))

static constexpr int STG      = 3;
static constexpr int TILE_B   = 128 * 128;        // 128 rows x 64 fp16 = 16 KB
static constexpr int STAGE_B  = 2 * TILE_B;       // Ah, Bh
static constexpr int SMEM_REQ = STG * STAGE_B;    // 96 KB
static constexpr int LDP      = 1028;             // padded ld for A (pos) matrix

// ---------------- scratch (B=4, L=2048, D=1024, 2M+1=1025) -----------------
__device__ __align__(1024) __half g_xh [8192u*1024u];
__device__ __align__(1024) __half g_wqh[1024u*1024u];
__device__ __align__(1024) __half g_wkh[1024u*1024u];
__device__ __align__(1024) __half g_wrh[1024u*1024u];
__device__ __align__(1024) __half g_tbh[1025u*1024u];
__device__ __align__(1024) __half g_quh[8192u*1024u];
__device__ __align__(1024) __half g_qvh[8192u*1024u];
__device__ __align__(1024) __half g_kh [8192u*1024u];
__device__ __align__(1024) __half g_rh [1025u*1024u];
__device__ __align__(1024) float  g_A  [8192u*(unsigned)LDP];

// ---------------------------- PTX helpers ----------------------------------
__device__ __forceinline__ uint32_t smem_u32(const void* p) {
    uint32_t a;
    asm("{ .reg .u64 t; cvta.to.shared.u64 t, %1; cvt.u32.u64 %0, t; }" : "=r"(a) : "l"(p));
    return a;
}
#define CP_ASYNC16(dst, src, pbytes) \
    asm volatile("cp.async.cg.shared.global [%0], [%1], 16, %2;" \
                 :: "r"(dst), "l"(src), "r"(pbytes))
#define CP_COMMIT() asm volatile("cp.async.commit_group;" ::: "memory")
#define CP_WAIT1()  asm volatile("cp.async.wait_group 1;"  ::: "memory")

#define LDSM_X4(r0,r1,r2,r3,a) \
    asm volatile("ldmatrix.sync.aligned.m8n8.x4.shared.b16 {%0,%1,%2,%3}, [%4];" \
                 : "=r"(r0), "=r"(r1), "=r"(r2), "=r"(r3) : "r"(a))
#define LDSM_X2(r0,r1,a) \
    asm volatile("ldmatrix.sync.aligned.m8n8.x2.shared.b16 {%0,%1}, [%2];" \
                 : "=r"(r0), "=r"(r1) : "r"(a))
#define MMA16816(c, a, b) \
    asm volatile("mma.sync.aligned.m16n8k16.row.col.f32.f16.f16.f32 " \
                 "{%0,%1,%2,%3}, {%4,%5,%6,%7}, {%8,%9}, {%0,%1,%2,%3};" \
                 : "+f"((c)[0]), "+f"((c)[1]), "+f"((c)[2]), "+f"((c)[3]) \
                 : "r"((a)[0]), "r"((a)[1]), "r"((a)[2]), "r"((a)[3]), \
                   "r"((b)[0]), "r"((b)[1]))

// ------------------- fused split kernel (one launch, 5 segments) ------------
__global__ void split5(const float* __restrict__ i0, const float* __restrict__ i1,
                       const float* __restrict__ i2, const float* __restrict__ i3,
                       const float* __restrict__ i4,
                       __half* __restrict__ h0, __half* __restrict__ h1,
                       __half* __restrict__ h2, __half* __restrict__ h3,
                       __half* __restrict__ h4,
                       int p0, int p1, int p2, int p3)
{
    int b = blockIdx.x;
    const float* in; __half* hi;
    if      (b < p0) { in = i0; hi = h0; }
    else if (b < p1) { in = i1; hi = h1; b -= p0; }
    else if (b < p2) { in = i2; hi = h2; b -= p1; }
    else if (b < p3) { in = i3; hi = h3; b -= p2; }
    else             { in = i4; hi = h4; b -= p3; }

    const int i = b * blockDim.x + threadIdx.x;
    float4 v = reinterpret_cast<const float4*>(in)[i];
    reinterpret_cast<__half2*>(hi)[i*2+0] =
        __halves2half2(__float2half_rn(v.x), __float2half_rn(v.y));
    reinterpret_cast<__half2*>(hi)[i*2+1] =
        __halves2half2(__float2half_rn(v.z), __float2half_rn(v.w));
}

// ---------------------- tile loader (cp.async, swizzled) --------------------
// Tile: 128 rows x 64 fp16 (128 B rows). Chunk c (16 B) of row r stored at
// r*128 + ((c ^ (r&7))*16)  -> conflict-free for both cp.async and ldmatrix.
__device__ __forceinline__ void load_tile(uint32_t dst, const __half* g,
                                          int row0, int rows_max, int k0, int ld,
                                          int tid, bool bchk) {
#pragma unroll
    for (int i = 0; i < 4; i++) {
        const int idx = tid + i * 256;
        const int r = idx >> 3, c = idx & 7;
        int row = row0 + r;
        unsigned p = 16;
        if (bchk && row >= rows_max) { p = 0; row = 0; }
        const __half* src = g + (size_t)row * ld + k0 + c * 8;
        const uint32_t d = dst + r * 128 + (((c ^ (r & 7))) << 4);
        CP_ASYNC16(d, src, p);
    }
}

// ------------------------------ GEMM kernel ---------------------------------
// acc = Ah * Bh (fp32 accumulate).
// MODE 0: fp32 store (ldc)                                   [GEMM4 -> A]
// MODE 1: (acc+bias1)->C0 fp16, (acc+bias2)->C1 fp16         [GEMM1 Qu/Qv]
// MODE 4: acc -> C0 fp16                                     [GEMM2 K, GEMM3 R]
// MODE 2: (acc + Apos[m, clip(m-n)+mr]) * scale -> C0        [GEMM5, batched]
template <int MODE, bool BCHK>
__global__ __launch_bounds__(256, 2)
void tc_gemm(const __half* __restrict__ gAh, const __half* __restrict__ gBh,
             void* C0, void* C1,
             const float* __restrict__ bias1, const float* __restrict__ bias2,
             const float* __restrict__ Apos,
             int M, int N, int ld, int ldc, int rowOffA, int rowOffB,
             long long sC, long long sP, int maxrel, int ldp, float scale, int nk)
{
    extern __shared__ __align__(128) char smem_raw[];
    const uint32_t sb = smem_u32(smem_raw);
    const int tid = threadIdx.x, lane = tid & 31, wid = tid >> 5;
    const int bm = blockIdx.y * 128, bn = blockIdx.x * 128, bz = blockIdx.z;
    const int wm = wid >> 2, wn = wid & 3;            // warp grid 2 x 4
    const int rA = bz * rowOffA + bm;
    const int rB = bz * rowOffB + bn;

    float acc[4][4][4];
#pragma unroll
    for (int mi = 0; mi < 4; mi++)
#pragma unroll
        for (int ni = 0; ni < 4; ni++)
#pragma unroll
            for (int q = 0; q < 4; q++) acc[mi][ni][q] = 0.f;

    auto load_stage = [&](int s, int t) {
        const uint32_t base = sb + s * STAGE_B;
        const int k0 = t * 64;
        load_tile(base,          gAh, rA, M, k0, ld, tid, BCHK);
        load_tile(base + TILE_B, gBh, rB, N, k0, ld, tid, BCHK);
    };

    load_stage(0, 0); CP_COMMIT();
    load_stage(1, 1); CP_COMMIT();

    // ldmatrix source addresses (lane-invariant parts)
    const int a_row = wm * 64 + (lane & 15);          // + mi*16
    const int a_cc  = lane >> 4;                      // + ks*2
    const int b_row = wn * 32 + (lane & 7);           // + ni*8
    const int b_cc  = (lane >> 3) & 1;                // + ks*2

    for (int t = 0; t < nk; t++) {
        CP_WAIT1();
        __syncthreads();
        if (t + 2 < nk) load_stage((t + 2) % STG, t + 2);
        CP_COMMIT();

        const uint32_t base = sb + (t % STG) * STAGE_B;
        const uint32_t sAh = base, sBh = base + TILE_B;

#pragma unroll
        for (int ks = 0; ks < 4; ks++) {
            uint32_t fAh[4][4], fBh[4][2];
#pragma unroll
            for (int mi = 0; mi < 4; mi++) {
                const int row = a_row + mi * 16;
                const int cc = ks * 2 + a_cc;
                const uint32_t off = row * 128 + (((cc ^ (row & 7))) << 4);
                LDSM_X4(fAh[mi][0], fAh[mi][1], fAh[mi][2], fAh[mi][3], sAh + off);
            }
#pragma unroll
            for (int ni = 0; ni < 4; ni++) {
                const int row = b_row + ni * 8;
                const int cc = ks * 2 + b_cc;
                const uint32_t off = row * 128 + (((cc ^ (row & 7))) << 4);
                LDSM_X2(fBh[ni][0], fBh[ni][1], sBh + off);
            }
#pragma unroll
            for (int mi = 0; mi < 4; mi++)
#pragma unroll
                for (int ni = 0; ni < 4; ni++) MMA16816(acc[mi][ni], fAh[mi], fBh[ni]);
        }
    }

    // ------------------------------ epilogue --------------------------------
    const int lr = lane >> 2, lc = (lane & 3) * 2;

#pragma unroll
    for (int mi = 0; mi < 4; mi++) {
#pragma unroll
        for (int ni = 0; ni < 4; ni++) {
            const float* cc = acc[mi][ni];
            const int n = bn + wn * 32 + ni * 8 + lc;
#pragma unroll
            for (int h = 0; h < 2; h++) {
                const int m = bm + wm * 64 + mi * 16 + lr + h * 8;
                const float v0 = cc[h * 2 + 0], v1 = cc[h * 2 + 1];
                if (MODE == 0) {
                    if (BCHK && m >= M) continue;
                    float* Cf = (float*)C0;
                    if (!BCHK || n + 1 < N) {
                        *reinterpret_cast<float2*>(Cf + (size_t)m * ldc + n) = make_float2(v0, v1);
                    } else if (n < N) {
                        Cf[(size_t)m * ldc + n] = v0;
                    }
                } else if (MODE == 4) {
                    if (BCHK && m >= M) continue;
                    __half* Ch = (__half*)C0;
                    *reinterpret_cast<__half2*>(Ch + (size_t)m * ldc + n) =
                        __halves2half2(__float2half_rn(v0), __float2half_rn(v1));
                } else if (MODE == 1) {
                    __half* Uh = (__half*)C0;
                    __half* Vh = (__half*)C1;
                    const size_t o = (size_t)m * ldc + n;
                    *reinterpret_cast<__half2*>(Uh + o) =
                        __halves2half2(__float2half_rn(v0 + bias1[n]),
                                       __float2half_rn(v1 + bias1[n + 1]));
                    *reinterpret_cast<__half2*>(Vh + o) =
                        __halves2half2(__float2half_rn(v0 + bias2[n]),
                                       __float2half_rn(v1 + bias2[n + 1]));
                } else { // MODE 2
                    const float* Ap = Apos + (size_t)bz * sP + (size_t)m * ldp + maxrel;
                    float* Ob = (float*)C0 + (size_t)bz * sC + (size_t)m * ldc;
                    int r0 = m - n;
                    r0 = r0 > maxrel ? maxrel : (r0 < -maxrel ? -maxrel : r0);
                    int r1 = m - (n + 1);
                    r1 = r1 > maxrel ? maxrel : (r1 < -maxrel ? -maxrel : r1);
                    *reinterpret_cast<float2*>(Ob + n) =
                        make_float2((v0 + Ap[r0]) * scale, (v1 + Ap[r1]) * scale);
                }
            }
        }
    }
}

// ------------------------------- host side ----------------------------------
extern "C" void kernel_launch(void* const* d_in, const int* in_sizes, int n_in,
                              void* d_out, int out_size)
{
    const float* x     = (const float*)d_in[0];
    const float* Wq    = (const float*)d_in[1];
    const float* Wk    = (const float*)d_in[2];
    const float* Wr    = (const float*)d_in[3];
    const float* u     = (const float*)d_in[4];
    const float* v     = (const float*)d_in[5];
    const float* table = (const float*)d_in[6];
    float* out = (float*)d_out;

    const int  D    = in_sizes[4];                    // 1024
    const int  NA   = in_sizes[6] / D;                // 1025
    const int  MREL = (NA - 1) / 2;                   // 512
    const long long BL = (long long)in_sizes[0] / D;  // 8192
    const int  L  = (int)((long long)out_size / BL);  // 2048
    const int  Bn = (int)(BL / L);                    // 4
    const int  nk = D / 64;                           // 16
    const float scale = 1.f / sqrtf((float)D);

    void *xh,*wqh,*wkh,*wrh,*tbh;
    void *quh,*qvh,*kh,*rh,*Aa;
    cudaGetSymbolAddress(&xh,  g_xh);
    cudaGetSymbolAddress(&wqh, g_wqh);
    cudaGetSymbolAddress(&wkh, g_wkh);
    cudaGetSymbolAddress(&wrh, g_wrh);
    cudaGetSymbolAddress(&tbh, g_tbh);
    cudaGetSymbolAddress(&quh, g_quh);
    cudaGetSymbolAddress(&qvh, g_qvh);
    cudaGetSymbolAddress(&kh,  g_kh);
    cudaGetSymbolAddress(&rh,  g_rh);
    cudaGetSymbolAddress(&Aa,  g_A);

    static bool attr_done = false;
    if (!attr_done) {
        cudaFuncSetAttribute(tc_gemm<1,false>, cudaFuncAttributeMaxDynamicSharedMemorySize, SMEM_REQ);
        cudaFuncSetAttribute(tc_gemm<4,false>, cudaFuncAttributeMaxDynamicSharedMemorySize, SMEM_REQ);
        cudaFuncSetAttribute(tc_gemm<4,true >, cudaFuncAttributeMaxDynamicSharedMemorySize, SMEM_REQ);
        cudaFuncSetAttribute(tc_gemm<0,true >, cudaFuncAttributeMaxDynamicSharedMemorySize, SMEM_REQ);
        cudaFuncSetAttribute(tc_gemm<2,false>, cudaFuncAttributeMaxDynamicSharedMemorySize, SMEM_REQ);
        attr_done = true;
    }

    // ---- fused split: one launch, fp16-round x, Wq, Wk, Wr, table ----
    {
        const int T = 256;
        const int bx = (int)(BL * D / 4) / T;   // 8192
        const int bw = (D * D / 4) / T;         // 1024
        const int bt = (NA * D / 4) / T;        // 1025
        const int p0 = bx, p1 = p0 + bw, p2 = p1 + bw, p3 = p2 + bw;
        split5<<<p3 + bt, T>>>(x, Wq, Wk, Wr, table,
            (__half*)xh, (__half*)wqh, (__half*)wkh, (__half*)wrh, (__half*)tbh,
            p0, p1, p2, p3);
    }

    const dim3 blk(256);

    // 1) Qu = round(x@Wq^T + u), Qv = round(x@Wq^T + v)  (MODE 1)
    tc_gemm<1,false><<<dim3(D/128, (int)(BL/128), 1), blk, SMEM_REQ>>>(
        (const __half*)xh, (const __half*)wqh,
        quh, qvh, u, v, nullptr,
        (int)BL, D, D, D, 0, 0, 0, 0, 0, 0, 0.f, nk);

    // 2) K = round(x@Wk^T)  (MODE 4)
    tc_gemm<4,false><<<dim3(D/128, (int)(BL/128), 1), blk, SMEM_REQ>>>(
        (const __half*)xh, (const __half*)wkh,
        kh, nullptr, nullptr, nullptr, nullptr,
        (int)BL, D, D, D, 0, 0, 0, 0, 0, 0, 0.f, nk);

    // 3) R = round(table@Wr^T)  (MODE 4, M bounds 1025)
    tc_gemm<4,true><<<dim3(D/128, SDIV(NA,128), 1), blk, SMEM_REQ>>>(
        (const __half*)tbh, (const __half*)wrh,
        rh, nullptr, nullptr, nullptr, nullptr,
        NA, D, D, D, 0, 0, 0, 0, 0, 0, 0.f, nk);

    // 4) A = Qv@R^T -> fp32, ldc=LDP  (MODE 0, N bounds 1025)
    tc_gemm<0,true><<<dim3(SDIV(NA,128), (int)(BL/128), 1), blk, SMEM_REQ>>>(
        (const __half*)qvh, (const __half*)rh,
        Aa, nullptr, nullptr, nullptr, nullptr,
        (int)BL, NA, D, LDP, 0, 0, 0, 0, 0, 0, 0.f, nk);

    // 5) out = (Qu@K^T + gather(A)) * scale, batched over B  (MODE 2)
    tc_gemm<2,false><<<dim3(L/128, L/128, Bn), blk, SMEM_REQ>>>(
        (const __half*)quh, (const __half*)kh,
        out, nullptr, nullptr, nullptr, (const float*)Aa,
        L, L, D, L, L, L,
        (long long)L * L, (long long)L * LDP, MREL, LDP, scale, nk);
}

// round 14
// speedup vs baseline: 2.7585x; 1.0617x over previous
#include <cuda_runtime.h>
#include <cuda_fp16.h>
#include <math.h>
#include <stdint.h>

// ---------------------------------------------------------------------------
// TransformerXL RPE via pure-fp16 mma.sync GEMMs (fp32 accumulate).
// out[b,i,j] = ( (Q+u)[b,i,:]·K[b,j,:] + A[b,i, clip(i-j)+M] ) / sqrt(D)
// Q = x@Wq^T, K = x@Wk^T, R = table@Wr^T, A = (Q+v)@R^T.
// All operands fp16, fp32 accumulate. rel_err ~4.3e-4 < 1e-3.
// Loop: CTA 128x128, warp 64x32, BK=64, 3-stage cp.async, 256 thr, 2 CTA/SM.
// G1/G2/G3 (independent) fused into ONE launch (1096 CTAs, segment decode
// by blockIdx) -> 4 co-residency waves instead of 5 + fewer launch gaps.
// (Resubmission of R13 — prior round hit a container-infra failure.)
// ---------------------------------------------------------------------------

#define SDIV(a,b) (((a)+(b)-1)/(b))

static constexpr int STG      = 3;
static constexpr int TILE_B   = 128 * 128;        // 128 rows x 64 fp16 = 16 KB
static constexpr int STAGE_B  = 2 * TILE_B;       // Ah, Bh
static constexpr int SMEM_REQ = STG * STAGE_B;    // 96 KB
static constexpr int LDP      = 1028;             // padded ld for A (pos) matrix

// ---------------- scratch (B=4, L=2048, D=1024, 2M+1=1025) -----------------
__device__ __align__(1024) __half g_xh [8192u*1024u];
__device__ __align__(1024) __half g_wqh[1024u*1024u];
__device__ __align__(1024) __half g_wkh[1024u*1024u];
__device__ __align__(1024) __half g_wrh[1024u*1024u];
__device__ __align__(1024) __half g_tbh[1025u*1024u];
__device__ __align__(1024) __half g_quh[8192u*1024u];
__device__ __align__(1024) __half g_qvh[8192u*1024u];
__device__ __align__(1024) __half g_kh [8192u*1024u];
__device__ __align__(1024) __half g_rh [1025u*1024u];
__device__ __align__(1024) float  g_A  [8192u*(unsigned)LDP];

// ---------------------------- PTX helpers ----------------------------------
__device__ __forceinline__ uint32_t smem_u32(const void* p) {
    uint32_t a;
    asm("{ .reg .u64 t; cvta.to.shared.u64 t, %1; cvt.u32.u64 %0, t; }" : "=r"(a) : "l"(p));
    return a;
}
#define CP_ASYNC16(dst, src, pbytes) \
    asm volatile("cp.async.cg.shared.global [%0], [%1], 16, %2;" \
                 :: "r"(dst), "l"(src), "r"(pbytes))
#define CP_COMMIT() asm volatile("cp.async.commit_group;" ::: "memory")
#define CP_WAIT1()  asm volatile("cp.async.wait_group 1;"  ::: "memory")

#define LDSM_X4(r0,r1,r2,r3,a) \
    asm volatile("ldmatrix.sync.aligned.m8n8.x4.shared.b16 {%0,%1,%2,%3}, [%4];" \
                 : "=r"(r0), "=r"(r1), "=r"(r2), "=r"(r3) : "r"(a))
#define LDSM_X2(r0,r1,a) \
    asm volatile("ldmatrix.sync.aligned.m8n8.x2.shared.b16 {%0,%1}, [%2];" \
                 : "=r"(r0), "=r"(r1) : "r"(a))
#define MMA16816(c, a, b) \
    asm volatile("mma.sync.aligned.m16n8k16.row.col.f32.f16.f16.f32 " \
                 "{%0,%1,%2,%3}, {%4,%5,%6,%7}, {%8,%9}, {%0,%1,%2,%3};" \
                 : "+f"((c)[0]), "+f"((c)[1]), "+f"((c)[2]), "+f"((c)[3]) \
                 : "r"((a)[0]), "r"((a)[1]), "r"((a)[2]), "r"((a)[3]), \
                   "r"((b)[0]), "r"((b)[1]))

// ------------------- fused split kernel (one launch, 5 segments) ------------
__global__ void split5(const float* __restrict__ i0, const float* __restrict__ i1,
                       const float* __restrict__ i2, const float* __restrict__ i3,
                       const float* __restrict__ i4,
                       __half* __restrict__ h0, __half* __restrict__ h1,
                       __half* __restrict__ h2, __half* __restrict__ h3,
                       __half* __restrict__ h4,
                       int p0, int p1, int p2, int p3)
{
    int b = blockIdx.x;
    const float* in; __half* hi;
    if      (b < p0) { in = i0; hi = h0; }
    else if (b < p1) { in = i1; hi = h1; b -= p0; }
    else if (b < p2) { in = i2; hi = h2; b -= p1; }
    else if (b < p3) { in = i3; hi = h3; b -= p2; }
    else             { in = i4; hi = h4; b -= p3; }

    const int i = b * blockDim.x + threadIdx.x;
    float4 v = reinterpret_cast<const float4*>(in)[i];
    reinterpret_cast<__half2*>(hi)[i*2+0] =
        __halves2half2(__float2half_rn(v.x), __float2half_rn(v.y));
    reinterpret_cast<__half2*>(hi)[i*2+1] =
        __halves2half2(__float2half_rn(v.z), __float2half_rn(v.w));
}

// ---------------------- tile loader (cp.async, swizzled) --------------------
// Tile: 128 rows x 64 fp16 (128 B rows). Chunk c (16 B) of row r stored at
// r*128 + ((c ^ (r&7))*16)  -> conflict-free for both cp.async and ldmatrix.
__device__ __forceinline__ void load_tile(uint32_t dst, const __half* g,
                                          int row0, int rows_max, int k0, int ld,
                                          int tid, bool bchk) {
#pragma unroll
    for (int i = 0; i < 4; i++) {
        const int idx = tid + i * 256;
        const int r = idx >> 3, c = idx & 7;
        int row = row0 + r;
        unsigned p = 16;
        if (bchk && row >= rows_max) { p = 0; row = 0; }
        const __half* src = g + (size_t)row * ld + k0 + c * 8;
        const uint32_t d = dst + r * 128 + (((c ^ (r & 7))) << 4);
        CP_ASYNC16(d, src, p);
    }
}

// --------------------------- shared GEMM mainloop ---------------------------
// acc[4][4][4] = Ah(128xK) * Bh(128xK)^T for this CTA tile. Proven pipeline:
// 3-stage cp.async, BK=64, swizzled ldmatrix, fp32-accum fp16 MMA.
__device__ __forceinline__ void gemm_core(
    uint32_t sb, const __half* __restrict__ gAh, const __half* __restrict__ gBh,
    int rA, int rB, int M, int N, int ld, int nk, bool bchk,
    int tid, int lane, int wid, float acc[4][4][4])
{
    const int wm = wid >> 2, wn = wid & 3;

    auto load_stage = [&](int s, int t) {
        const uint32_t base = sb + s * STAGE_B;
        const int k0 = t * 64;
        load_tile(base,          gAh, rA, M, k0, ld, tid, bchk);
        load_tile(base + TILE_B, gBh, rB, N, k0, ld, tid, bchk);
    };

    load_stage(0, 0); CP_COMMIT();
    load_stage(1, 1); CP_COMMIT();

    const int a_row = wm * 64 + (lane & 15);          // + mi*16
    const int a_cc  = lane >> 4;                      // + ks*2
    const int b_row = wn * 32 + (lane & 7);           // + ni*8
    const int b_cc  = (lane >> 3) & 1;                // + ks*2

    for (int t = 0; t < nk; t++) {
        CP_WAIT1();
        __syncthreads();
        if (t + 2 < nk) load_stage((t + 2) % STG, t + 2);
        CP_COMMIT();

        const uint32_t base = sb + (t % STG) * STAGE_B;
        const uint32_t sAh = base, sBh = base + TILE_B;

#pragma unroll
        for (int ks = 0; ks < 4; ks++) {
            uint32_t fAh[4][4], fBh[4][2];
#pragma unroll
            for (int mi = 0; mi < 4; mi++) {
                const int row = a_row + mi * 16;
                const int cc = ks * 2 + a_cc;
                const uint32_t off = row * 128 + (((cc ^ (row & 7))) << 4);
                LDSM_X4(fAh[mi][0], fAh[mi][1], fAh[mi][2], fAh[mi][3], sAh + off);
            }
#pragma unroll
            for (int ni = 0; ni < 4; ni++) {
                const int row = b_row + ni * 8;
                const int cc = ks * 2 + b_cc;
                const uint32_t off = row * 128 + (((cc ^ (row & 7))) << 4);
                LDSM_X2(fBh[ni][0], fBh[ni][1], sBh + off);
            }
#pragma unroll
            for (int mi = 0; mi < 4; mi++)
#pragma unroll
                for (int ni = 0; ni < 4; ni++) MMA16816(acc[mi][ni], fAh[mi], fBh[ni]);
        }
    }
}

// -------------------- fused G1+G2+G3 kernel (one launch) --------------------
// seg0 [0,g1):       Qu/Qv = x@Wq^T + u/v   (M=BL)
// seg1 [g1,g1+g2):   K = x@Wk^T             (M=BL)
// seg2 [g1+g2,...):  R = table@Wr^T         (M=NA, bounds-checked)
__global__ __launch_bounds__(256, 2)
void tc_gemm_f123(const __half* __restrict__ xh,  const __half* __restrict__ wqh,
                  const __half* __restrict__ wkh,
                  const __half* __restrict__ tbh, const __half* __restrict__ wrh,
                  __half* __restrict__ quh, __half* __restrict__ qvh,
                  __half* __restrict__ kh,  __half* __restrict__ rh,
                  const float* __restrict__ u, const float* __restrict__ v,
                  int BLi, int NA, int D, int nk, int g1, int g12)
{
    extern __shared__ __align__(128) char smem_raw[];
    const uint32_t sb = smem_u32(smem_raw);
    const int tid = threadIdx.x, lane = tid & 31, wid = tid >> 5;

    int b = blockIdx.x;
    int seg; const __half *gA, *gB; int M;
    if (b < g1)       { seg = 0; gA = xh;  gB = wqh; M = BLi; }
    else if (b < g12) { seg = 1; gA = xh;  gB = wkh; M = BLi; b -= g1; }
    else              { seg = 2; gA = tbh; gB = wrh; M = NA;  b -= g12; }

    const int nx = D >> 7;                       // 8 column tiles (N = D)
    const int bn = (b % nx) * 128;
    const int bm = (b / nx) * 128;
    const bool bchk = (seg == 2);

    float acc[4][4][4];
#pragma unroll
    for (int mi = 0; mi < 4; mi++)
#pragma unroll
        for (int ni = 0; ni < 4; ni++)
#pragma unroll
            for (int q = 0; q < 4; q++) acc[mi][ni][q] = 0.f;

    gemm_core(sb, gA, gB, bm, bn, M, D, D, nk, bchk, tid, lane, wid, acc);

    const int wm = wid >> 2, wn = wid & 3;
    const int lr = lane >> 2, lc = (lane & 3) * 2;

#pragma unroll
    for (int mi = 0; mi < 4; mi++) {
#pragma unroll
        for (int ni = 0; ni < 4; ni++) {
            const float* cc = acc[mi][ni];
            const int n = bn + wn * 32 + ni * 8 + lc;
#pragma unroll
            for (int h = 0; h < 2; h++) {
                const int m = bm + wm * 64 + mi * 16 + lr + h * 8;
                const float v0 = cc[h * 2 + 0], v1 = cc[h * 2 + 1];
                if (seg == 0) {
                    const size_t o = (size_t)m * D + n;
                    *reinterpret_cast<__half2*>(quh + o) =
                        __halves2half2(__float2half_rn(v0 + u[n]),
                                       __float2half_rn(v1 + u[n + 1]));
                    *reinterpret_cast<__half2*>(qvh + o) =
                        __halves2half2(__float2half_rn(v0 + v[n]),
                                       __float2half_rn(v1 + v[n + 1]));
                } else {
                    if (seg == 2 && m >= M) continue;
                    __half* C = (seg == 1) ? kh : rh;
                    *reinterpret_cast<__half2*>(C + (size_t)m * D + n) =
                        __halves2half2(__float2half_rn(v0), __float2half_rn(v1));
                }
            }
        }
    }
}

// ------------------------------ GEMM kernel ---------------------------------
// MODE 0: fp32 store (ldc)                                   [GEMM4 -> A]
// MODE 2: (acc + Apos[m, clip(m-n)+mr]) * scale -> C0        [GEMM5, batched]
template <int MODE, bool BCHK>
__global__ __launch_bounds__(256, 2)
void tc_gemm(const __half* __restrict__ gAh, const __half* __restrict__ gBh,
             void* C0,
             const float* __restrict__ Apos,
             int M, int N, int ld, int ldc, int rowOffA, int rowOffB,
             long long sC, long long sP, int maxrel, int ldp, float scale, int nk)
{
    extern __shared__ __align__(128) char smem_raw[];
    const uint32_t sb = smem_u32(smem_raw);
    const int tid = threadIdx.x, lane = tid & 31, wid = tid >> 5;
    const int bm = blockIdx.y * 128, bn = blockIdx.x * 128, bz = blockIdx.z;
    const int rA = bz * rowOffA + bm;
    const int rB = bz * rowOffB + bn;

    float acc[4][4][4];
#pragma unroll
    for (int mi = 0; mi < 4; mi++)
#pragma unroll
        for (int ni = 0; ni < 4; ni++)
#pragma unroll
            for (int q = 0; q < 4; q++) acc[mi][ni][q] = 0.f;

    gemm_core(sb, gAh, gBh, rA, rB, M, N, ld, nk, BCHK, tid, lane, wid, acc);

    const int wm = wid >> 2, wn = wid & 3;
    const int lr = lane >> 2, lc = (lane & 3) * 2;

#pragma unroll
    for (int mi = 0; mi < 4; mi++) {
#pragma unroll
        for (int ni = 0; ni < 4; ni++) {
            const float* cc = acc[mi][ni];
            const int n = bn + wn * 32 + ni * 8 + lc;
#pragma unroll
            for (int h = 0; h < 2; h++) {
                const int m = bm + wm * 64 + mi * 16 + lr + h * 8;
                const float v0 = cc[h * 2 + 0], v1 = cc[h * 2 + 1];
                if (MODE == 0) {
                    if (BCHK && m >= M) continue;
                    float* Cf = (float*)C0;
                    if (!BCHK || n + 1 < N) {
                        *reinterpret_cast<float2*>(Cf + (size_t)m * ldc + n) = make_float2(v0, v1);
                    } else if (n < N) {
                        Cf[(size_t)m * ldc + n] = v0;
                    }
                } else { // MODE 2
                    const float* Ap = Apos + (size_t)bz * sP + (size_t)m * ldp + maxrel;
                    float* Ob = (float*)C0 + (size_t)bz * sC + (size_t)m * ldc;
                    int r0 = m - n;
                    r0 = r0 > maxrel ? maxrel : (r0 < -maxrel ? -maxrel : r0);
                    int r1 = m - (n + 1);
                    r1 = r1 > maxrel ? maxrel : (r1 < -maxrel ? -maxrel : r1);
                    *reinterpret_cast<float2*>(Ob + n) =
                        make_float2((v0 + Ap[r0]) * scale, (v1 + Ap[r1]) * scale);
                }
            }
        }
    }
}

// ------------------------------- host side ----------------------------------
extern "C" void kernel_launch(void* const* d_in, const int* in_sizes, int n_in,
                              void* d_out, int out_size)
{
    const float* x     = (const float*)d_in[0];
    const float* Wq    = (const float*)d_in[1];
    const float* Wk    = (const float*)d_in[2];
    const float* Wr    = (const float*)d_in[3];
    const float* u     = (const float*)d_in[4];
    const float* v     = (const float*)d_in[5];
    const float* table = (const float*)d_in[6];
    float* out = (float*)d_out;

    const int  D    = in_sizes[4];                    // 1024
    const int  NA   = in_sizes[6] / D;                // 1025
    const int  MREL = (NA - 1) / 2;                   // 512
    const long long BL = (long long)in_sizes[0] / D;  // 8192
    const int  L  = (int)((long long)out_size / BL);  // 2048
    const int  Bn = (int)(BL / L);                    // 4
    const int  nk = D / 64;                           // 16
    const float scale = 1.f / sqrtf((float)D);

    void *xh,*wqh,*wkh,*wrh,*tbh;
    void *quh,*qvh,*kh,*rh,*Aa;
    cudaGetSymbolAddress(&xh,  g_xh);
    cudaGetSymbolAddress(&wqh, g_wqh);
    cudaGetSymbolAddress(&wkh, g_wkh);
    cudaGetSymbolAddress(&wrh, g_wrh);
    cudaGetSymbolAddress(&tbh, g_tbh);
    cudaGetSymbolAddress(&quh, g_quh);
    cudaGetSymbolAddress(&qvh, g_qvh);
    cudaGetSymbolAddress(&kh,  g_kh);
    cudaGetSymbolAddress(&rh,  g_rh);
    cudaGetSymbolAddress(&Aa,  g_A);

    static bool attr_done = false;
    if (!attr_done) {
        cudaFuncSetAttribute(tc_gemm_f123,     cudaFuncAttributeMaxDynamicSharedMemorySize, SMEM_REQ);
        cudaFuncSetAttribute(tc_gemm<0,true >, cudaFuncAttributeMaxDynamicSharedMemorySize, SMEM_REQ);
        cudaFuncSetAttribute(tc_gemm<2,false>, cudaFuncAttributeMaxDynamicSharedMemorySize, SMEM_REQ);
        attr_done = true;
    }

    // ---- fused split: one launch, fp16-round x, Wq, Wk, Wr, table ----
    {
        const int T = 256;
        const int bx = (int)(BL * D / 4) / T;   // 8192
        const int bw = (D * D / 4) / T;         // 1024
        const int bt = (NA * D / 4) / T;        // 1025
        const int p0 = bx, p1 = p0 + bw, p2 = p1 + bw, p3 = p2 + bw;
        split5<<<p3 + bt, T>>>(x, Wq, Wk, Wr, table,
            (__half*)xh, (__half*)wqh, (__half*)wkh, (__half*)wrh, (__half*)tbh,
            p0, p1, p2, p3);
    }

    const dim3 blk(256);

    // ---- fused G1+G2+G3: one launch (1096 CTAs) ----
    {
        const int nx = D / 128;                       // 8
        const int g1 = nx * (int)(BL / 128);          // 512
        const int g2 = g1;                            // 512
        const int g3 = nx * SDIV(NA, 128);            // 72
        tc_gemm_f123<<<g1 + g2 + g3, blk, SMEM_REQ>>>(
            (const __half*)xh, (const __half*)wqh, (const __half*)wkh,
            (const __half*)tbh, (const __half*)wrh,
            (__half*)quh, (__half*)qvh, (__half*)kh, (__half*)rh,
            u, v, (int)BL, NA, D, nk, g1, g1 + g2);
    }

    // 4) A = Qv@R^T -> fp32, ldc=LDP  (MODE 0, N bounds 1025)
    tc_gemm<0,true><<<dim3(SDIV(NA,128), (int)(BL/128), 1), blk, SMEM_REQ>>>(
        (const __half*)qvh, (const __half*)rh,
        Aa, nullptr,
        (int)BL, NA, D, LDP, 0, 0, 0, 0, 0, 0, 0.f, nk);

    // 5) out = (Qu@K^T + gather(A)) * scale, batched over B  (MODE 2)
    tc_gemm<2,false><<<dim3(L/128, L/128, Bn), blk, SMEM_REQ>>>(
        (const __half*)quh, (const __half*)kh,
        out, (const float*)Aa,
        L, L, D, L, L, L,
        (long long)L * L, (long long)L * LDP, MREL, LDP, scale, nk);
}